// round 9
// baseline (speedup 1.0000x reference)
#include <cuda_runtime.h>
#include <cuda_bf16.h>

#define FULLMASK 0xffffffffu
typedef unsigned long long u64;

// Two batch elements per warp, SIMD-packed in f32x2:
//   sr[j] = (reA, reB), si[j] = (imA, imB)  for amplitude slot j (0..7)
// Qubit -> amplitude-index-bit mapping (R4 layout):
//   q3->bit0, q5->bit1, q7->bit2  (register bits j)
//   q0->L0, q1->L1, q2->L2, q4->L3, q6->L4  (lane bits)
// amp index = (lane << 3) | j

__device__ __forceinline__ u64 pk(float lo, float hi) {
    u64 r; asm("mov.b64 %0, {%1, %2};" : "=l"(r) : "f"(lo), "f"(hi)); return r;
}
__device__ __forceinline__ void upk(u64 v, float& x, float& y) {
    asm("mov.b64 {%0, %1}, %2;" : "=f"(x), "=f"(y) : "l"(v));
}
__device__ __forceinline__ u64 f2mul(u64 a, u64 b) {
    u64 r; asm("mul.rn.f32x2 %0, %1, %2;" : "=l"(r) : "l"(a), "l"(b)); return r;
}
__device__ __forceinline__ u64 f2fma(u64 a, u64 b, u64 c) {
    u64 r; asm("fma.rn.f32x2 %0, %1, %2, %3;" : "=l"(r) : "l"(a), "l"(b), "l"(c)); return r;
}
__device__ __forceinline__ u64 f2add(u64 a, u64 b) {
    u64 r; asm("add.rn.f32x2 %0, %1, %2;" : "=l"(r) : "l"(a), "l"(b)); return r;
}
__device__ __forceinline__ u64 shx64(u64 v, int m) { return __shfl_xor_sync(FULLMASK, v, m); }

// ---- Ry on index-bit Tb: cc=(c,c) pp=(s,s) nn=(-s,-s) ----
template <int Tb>
__device__ __forceinline__ void applyRy(u64 sr[8], u64 si[8], u64 cc, u64 pp, u64 nn, int lane) {
    if constexpr (Tb < 3) {
        constexpr int m = 1 << Tb;
#pragma unroll
        for (int j = 0; j < 8; j++) {
            if (!(j & m)) {
                u64 ar = sr[j], ai = si[j], br = sr[j | m], bi = si[j | m];
                sr[j]     = f2fma(cc, ar, f2mul(nn, br));
                si[j]     = f2fma(cc, ai, f2mul(nn, bi));
                sr[j | m] = f2fma(cc, br, f2mul(pp, ar));
                si[j | m] = f2fma(cc, bi, f2mul(pp, ai));
            }
        }
    } else {
        constexpr int lb = 1 << (Tb - 3);
        u64 sg = (lane & lb) ? pp : nn;
#pragma unroll
        for (int j = 0; j < 8; j++) {
            u64 orr = shx64(sr[j], lb);
            u64 oii = shx64(si[j], lb);
            sr[j] = f2fma(cc, sr[j], f2mul(sg, orr));
            si[j] = f2fma(cc, si[j], f2mul(sg, oii));
        }
    }
}

// ---- controlled rotation: K=0 rx, K=1 ry, K=2 rz ----
// G[0]=(c,c) G[1]=(s,s) G[2]=(-s,-s)
template <int K, int Cb, int Tb>
__device__ __forceinline__ void applyCR(u64 sr[8], u64 si[8], const u64* __restrict__ G, int lane) {
    u64 cc = G[0], ps = G[1], ns = G[2];
    if constexpr (K == 2) {
        // CRz diagonal: t=0: (c - i s)  t=1: (c + i s)
        bool laneT = (Tb >= 3) ? (((lane >> (Tb - 3)) & 1) != 0) : false;
        if constexpr (Cb < 3) {
#pragma unroll
            for (int j = 0; j < 8; j++) {
                if (j & (1 << Cb)) {
                    bool tb = (Tb < 3) ? (((j >> Tb) & 1) != 0) : laneT;
                    u64 f1 = tb ? ns : ps, f2 = tb ? ps : ns;
                    u64 nr = f2fma(cc, sr[j], f2mul(f1, si[j]));
                    u64 ni = f2fma(cc, si[j], f2mul(f2, sr[j]));
                    sr[j] = nr; si[j] = ni;
                }
            }
        } else {
            bool lc = ((lane >> (Cb - 3)) & 1) != 0;
#pragma unroll
            for (int j = 0; j < 8; j++) {
                bool tb = (Tb < 3) ? (((j >> Tb) & 1) != 0) : laneT;
                u64 f1 = tb ? ns : ps, f2 = tb ? ps : ns;
                u64 nr = f2fma(cc, sr[j], f2mul(f1, si[j]));
                u64 ni = f2fma(cc, si[j], f2mul(f2, sr[j]));
                if (lc) { sr[j] = nr; si[j] = ni; }
            }
        }
    } else if constexpr (Tb < 3) {
        constexpr int tm = 1 << Tb;
        bool lc = (Cb >= 3) ? (((lane >> (Cb - 3)) & 1) != 0) : false;
#pragma unroll
        for (int j = 0; j < 8; j++) {
            if (!(j & tm) && (Cb >= 3 || ((j >> Cb) & 1))) {
                u64 ar = sr[j], ai = si[j], br = sr[j | tm], bi = si[j | tm];
                u64 nar, nai, nbr, nbi;
                if constexpr (K == 0) {   // rx
                    nar = f2fma(cc, ar, f2mul(ps, bi));
                    nai = f2fma(cc, ai, f2mul(ns, br));
                    nbr = f2fma(cc, br, f2mul(ps, ai));
                    nbi = f2fma(cc, bi, f2mul(ns, ar));
                } else {                  // ry
                    nar = f2fma(cc, ar, f2mul(ns, br));
                    nai = f2fma(cc, ai, f2mul(ns, bi));
                    nbr = f2fma(cc, br, f2mul(ps, ar));
                    nbi = f2fma(cc, bi, f2mul(ps, ai));
                }
                if constexpr (Cb < 3) { sr[j]=nar; si[j]=nai; sr[j|tm]=nbr; si[j|tm]=nbi; }
                else if (lc) { sr[j]=nar; si[j]=nai; sr[j|tm]=nbr; si[j|tm]=nbi; }
            }
        }
    } else {
        constexpr int lb = 1 << (Tb - 3);
        u64 sg = (lane & lb) ? ps : ns;
        if constexpr (Cb < 3) {
#pragma unroll
            for (int j = 0; j < 8; j++) {
                if (j & (1 << Cb)) {
                    u64 orr = shx64(sr[j], lb);
                    u64 oii = shx64(si[j], lb);
                    if constexpr (K == 0) {
                        sr[j] = f2fma(cc, sr[j], f2mul(ps, oii));
                        si[j] = f2fma(cc, si[j], f2mul(ns, orr));
                    } else {
                        sr[j] = f2fma(cc, sr[j], f2mul(sg, orr));
                        si[j] = f2fma(cc, si[j], f2mul(sg, oii));
                    }
                }
            }
        } else {
            bool lc = ((lane >> (Cb - 3)) & 1) != 0;
#pragma unroll
            for (int j = 0; j < 8; j++) {
                u64 orr = shx64(sr[j], lb);
                u64 oii = shx64(si[j], lb);
                u64 nr, ni;
                if constexpr (K == 0) {
                    nr = f2fma(cc, sr[j], f2mul(ps, oii));
                    ni = f2fma(cc, si[j], f2mul(ns, orr));
                } else {
                    nr = f2fma(cc, sr[j], f2mul(sg, orr));
                    ni = f2fma(cc, si[j], f2mul(sg, oii));
                }
                if (lc) { sr[j] = nr; si[j] = ni; }
            }
        }
    }
}

// ---- u3 gate; 12 packed consts per gate:
// row_lo [0..5]: {u00r, 0, 0, u01r, u01i, -u01i}
// row_hi [6..11]: {u11r, u11i, -u11i, u10r, u10i, -u10i}
// row math: out_r = Ar*own_r + Ain*own_i + Br*oth_r + Bin*oth_i
//           out_i = Ar*own_i + Aip*own_r + Br*oth_i + Bip*oth_r
template <int Tb>
__device__ __forceinline__ void applyU3(u64 sr[8], u64 si[8], const u64* __restrict__ U, int lane) {
    if constexpr (Tb < 3) {
        constexpr int m = 1 << Tb;
#pragma unroll
        for (int j = 0; j < 8; j++) {
            if (!(j & m)) {
                u64 ar = sr[j], ai = si[j], br = sr[j | m], bi = si[j | m];
                sr[j]     = f2fma(U[0], ar, f2fma(U[3], br, f2mul(U[5], bi)));
                si[j]     = f2fma(U[0], ai, f2fma(U[3], bi, f2mul(U[4], br)));
                sr[j | m] = f2fma(U[6], br, f2fma(U[8], bi, f2fma(U[9], ar, f2mul(U[11], ai))));
                si[j | m] = f2fma(U[6], bi, f2fma(U[7], br, f2fma(U[9], ai, f2mul(U[10], ar))));
            }
        }
    } else {
        constexpr int lb = 1 << (Tb - 3);
        const u64* R = U + (((lane >> (Tb - 3)) & 1) ? 6 : 0);
        u64 R0 = R[0], R1 = R[1], R2 = R[2], R3 = R[3], R4 = R[4], R5 = R[5];
#pragma unroll
        for (int j = 0; j < 8; j++) {
            u64 orr = shx64(sr[j], lb);
            u64 oii = shx64(si[j], lb);
            u64 nr = f2fma(R0, sr[j], f2fma(R2, si[j], f2fma(R3, orr, f2mul(R5, oii))));
            u64 ni = f2fma(R0, si[j], f2fma(R1, sr[j], f2fma(R3, oii, f2mul(R4, orr))));
            sr[j] = nr; si[j] = ni;
        }
    }
}

// ---- CNOT ----
template <int Cb, int Tb>
__device__ __forceinline__ void cnot(u64 sr[8], u64 si[8], int lane) {
    if constexpr (Tb < 3) {
        constexpr int tm = 1 << Tb;
        bool lc = (Cb >= 3) ? (((lane >> (Cb - 3)) & 1) != 0) : false;
#pragma unroll
        for (int j = 0; j < 8; j++) {
            if (!(j & tm)) {
                bool ctrl = (Cb < 3) ? (((j >> Cb) & 1) != 0) : lc;
                if (ctrl) {
                    u64 t = sr[j]; sr[j] = sr[j | tm]; sr[j | tm] = t;
                    t = si[j]; si[j] = si[j | tm]; si[j | tm] = t;
                }
            }
        }
    } else {
        constexpr int lb = 1 << (Tb - 3);
        if constexpr (Cb < 3) {
#pragma unroll
            for (int j = 0; j < 8; j++) {
                if (j & (1 << Cb)) {
                    sr[j] = shx64(sr[j], lb);
                    si[j] = shx64(si[j], lb);
                }
            }
        } else {
            bool lc = ((lane >> (Cb - 3)) & 1) != 0;
#pragma unroll
            for (int j = 0; j < 8; j++) {
                u64 orr = shx64(sr[j], lb);
                u64 oii = shx64(si[j], lb);
                if (lc) { sr[j] = orr; si[j] = oii; }
            }
        }
    }
}

// fused cnot<3,4>; cnot<4,5> — pure lane permutation
__device__ __forceinline__ void ring_head(u64 sr[8], u64 si[8], int lane) {
    int src = lane ^ (((lane >> 1) & 1) << 2) ^ ((lane & 1) << 1);
#pragma unroll
    for (int j = 0; j < 8; j++) {
        sr[j] = __shfl_sync(FULLMASK, sr[j], src);
        si[j] = __shfl_sync(FULLMASK, si[j], src);
    }
}

__device__ __forceinline__ void ring_layer(u64 sr[8], u64 si[8], int lane) {
    ring_head(sr, si, lane);   // (q0,q1), (q1,q2)
    cnot<5, 0>(sr, si, lane);  // (q2,q3)
    cnot<0, 6>(sr, si, lane);  // (q3,q4)
    cnot<6, 1>(sr, si, lane);  // (q4,q5)
    cnot<1, 7>(sr, si, lane);  // (q5,q6)
    cnot<7, 2>(sr, si, lane);  // (q6,q7)
    cnot<2, 3>(sr, si, lane);  // (q7,q0)
}

template <int K>
__device__ __forceinline__ void runBranch(u64 sr[8], u64 si[8],
                                          const u64* __restrict__ CR,
                                          const u64* __restrict__ UM,
                                          int lane, u64& e3p, u64& e7p) {
#define CRG(i, Cb, Tb) applyCR<K, Cb, Tb>(sr, si, CR + (i) * 3, lane);
#define U3G(i, Tb) applyU3<Tb>(sr, si, UM + (i) * 12, lane);
    // PAIRS_A
    CRG(0, 3, 4)  // (0,1)
    CRG(1, 5, 0)  // (2,3)
    CRG(2, 6, 1)  // (4,5)
    CRG(3, 7, 2)  // (6,7)
    CRG(4, 4, 5)  // (1,2)
    CRG(5, 0, 6)  // (3,4)
    CRG(6, 1, 7)  // (5,6)
    // u3 on wires 1,3,5,7 -> bits 4,0,1,2
    U3G(0, 4) U3G(1, 0) U3G(2, 1) U3G(3, 2)
    // PAIRS_B
    CRG(7, 4, 0)  // (1,3)
    CRG(8, 1, 2)  // (5,7)
    CRG(9, 0, 1)  // (3,5)
    // u3 on wires 3,7 -> bits 0,2
    U3G(4, 0) U3G(5, 2)
#undef CRG
#undef U3G

    u64 a3 = pk(0.f, 0.f), a7 = pk(0.f, 0.f);
    u64 m1 = pk(-1.f, -1.f);
#pragma unroll
    for (int j = 0; j < 8; j++) {
        u64 q = f2fma(sr[j], sr[j], f2mul(si[j], si[j]));  // (|A|^2, |B|^2)
        u64 qn = f2mul(q, m1);
        a3 = f2add(a3, (j & 1) ? qn : q);
        a7 = f2add(a7, (j & 4) ? qn : q);
    }
#pragma unroll
    for (int o = 16; o > 0; o >>= 1) {
        a3 = f2add(a3, shx64(a3, o));
        a7 = f2add(a7, shx64(a7, o));
    }
    e3p = a3; e7p = a7;
}

__global__ __launch_bounds__(256) void qcnn_kernel(
    const float* __restrict__ theta, const float* __restrict__ phi,
    const float* __restrict__ angles_x, const float* __restrict__ angles_y,
    const float* __restrict__ angles_z,
    const float* __restrict__ u3_x, const float* __restrict__ u3_y,
    const float* __restrict__ u3_z,
    const float* __restrict__ W1, const float* __restrict__ b1,
    const float* __restrict__ W2, const float* __restrict__ b2,
    float* __restrict__ out, int B)
{
    __shared__ u64 shCR[3 * 10 * 3];    // (c,c),(s,s),(-s,-s)
    __shared__ u64 shU3[3 * 6 * 12];    // two 6-entry rows per gate
    __shared__ u64 shP0[8 * 512];       // psi0 snapshot: [warp][16 slots][lane]
    __shared__ float shW1[72], shB1[12], shW2[12];
    __shared__ float shB2;

    int tid = threadIdx.x;
    if (tid < 30) {
        int b = tid / 10, i = tid % 10;
        const float* ang = (b == 0) ? angles_x : (b == 1) ? angles_y : angles_z;
        float sn, c;
        sincosf(0.5f * ang[i], &sn, &c);
        u64* g = &shCR[tid * 3];
        g[0] = pk(c, c);
        g[1] = pk(sn, sn);
        g[2] = pk(-sn, -sn);
    }
    if (tid >= 32 && tid < 50) {
        int k = tid - 32;
        int b = k / 6, i = k % 6;
        const float* up = ((b == 0) ? u3_x : (b == 1) ? u3_y : u3_z) + i * 3;
        float th = up[0], ph = up[1], lm = up[2];
        float sn, c;    sincosf(0.5f * th, &sn, &c);
        float sl, cl;   sincosf(lm, &sl, &cl);
        float sp, cp;   sincosf(ph, &sp, &cp);
        float spl, cpl; sincosf(ph + lm, &spl, &cpl);
        // u00=(c,0) u01=(-cl*sn, -sl*sn) u10=(cp*sn, sp*sn) u11=(cpl*c, spl*c)
        float u01r = -cl * sn, u01i = -sl * sn;
        float u10r = cp * sn, u10i = sp * sn;
        float u11r = cpl * c, u11i = spl * c;
        u64* g = &shU3[k * 12];
        g[0]  = pk(c, c);        g[1]  = pk(0.f, 0.f);   g[2]  = pk(0.f, 0.f);
        g[3]  = pk(u01r, u01r);  g[4]  = pk(u01i, u01i); g[5]  = pk(-u01i, -u01i);
        g[6]  = pk(u11r, u11r);  g[7]  = pk(u11i, u11i); g[8]  = pk(-u11i, -u11i);
        g[9]  = pk(u10r, u10r);  g[10] = pk(u10i, u10i); g[11] = pk(-u10i, -u10i);
    }
    if (tid >= 64 && tid < 136)  shW1[tid - 64] = W1[tid - 64];
    if (tid >= 136 && tid < 148) shB1[tid - 136] = b1[tid - 136];
    if (tid >= 148 && tid < 160) shW2[tid - 148] = W2[tid - 148];
    if (tid == 160) shB2 = b2[0];
    __syncthreads();

    int warp = tid >> 5;
    int lane = tid & 31;
    int e0 = (blockIdx.x * 8 + warp) * 2;
    if (e0 >= B) return;
    int e1 = min(e0 + 1, B - 1);

    float thA = theta[e0], thB = theta[e1];
    float phA = phi[e0],   phB = phi[e1];

    float syA, cyA, syB, cyB;
    sincosf(0.5f * thA, &syA, &cyA);
    sincosf(0.5f * thB, &syB, &cyB);
    u64 cc = pk(cyA, cyB), pp = pk(syA, syB), nn = pk(-syA, -syB);

    // Rz-layer combined diagonal: amp *= cis(ph * (popc(idx) - 4))
    float c1xA, c1yA, c1xB, c1yB;
    sincosf(phA, &c1yA, &c1xA);
    sincosf(phB, &c1yB, &c1xB);
    float plf = (float)(__popc(lane) - 4);
    float cl0xA, cl0yA, cl0xB, cl0yB;
    sincosf(phA * plf, &cl0yA, &cl0xA);
    sincosf(phB * plf, &cl0yB, &cl0xB);
    u64 c1x = pk(c1xA, c1xB), c1y = pk(c1yA, c1yB), c1yn = pk(-c1yA, -c1yB);
    u64 px[4], pyp[4], pyn[4];
    px[0] = pk(cl0xA, cl0xB);
    pyp[0] = pk(cl0yA, cl0yB);
    pyn[0] = pk(-cl0yA, -cl0yB);
#pragma unroll
    for (int d = 0; d < 3; d++) {
        px[d + 1]  = f2fma(c1x, px[d], f2mul(c1yn, pyp[d]));
        pyp[d + 1] = f2fma(c1y, px[d], f2mul(c1x, pyp[d]));
        pyn[d + 1] = f2fma(c1yn, px[d], f2mul(c1x, pyn[d]));
    }
    const int POPC[8] = {0, 1, 1, 2, 1, 2, 2, 3};

    // ---- cycle 1: closed-form product state ----
    u64 sr[8], si[8];
    {
        u64 base = pk(1.f, 1.f);
#pragma unroll
        for (int k = 0; k < 5; k++) base = f2mul(base, ((lane >> k) & 1) ? pp : cc);
        u64 c2 = f2mul(cc, cc), s2 = f2mul(pp, pp);
        u64 f0 = f2mul(c2, cc);
        u64 f1 = f2mul(c2, pp);
        u64 f2_ = f2mul(cc, s2);
        u64 f3 = f2mul(pp, s2);
        u64 fj[8] = {f0, f1, f1, f2_, f1, f2_, f2_, f3};
#pragma unroll
        for (int j = 0; j < 8; j++) {
            u64 w = f2mul(base, fj[j]);
            int d = POPC[j];
            sr[j] = f2mul(px[d], w);
            si[j] = f2mul(pyp[d], w);
        }
    }
    ring_layer(sr, si, lane);

    // ---- cycles 2..4 ----
#pragma unroll 1
    for (int cyc = 0; cyc < 3; cyc++) {
        applyRy<3>(sr, si, cc, pp, nn, lane);
        applyRy<0>(sr, si, cc, pp, nn, lane);
        applyRy<4>(sr, si, cc, pp, nn, lane);
        applyRy<1>(sr, si, cc, pp, nn, lane);
        applyRy<5>(sr, si, cc, pp, nn, lane);
        applyRy<2>(sr, si, cc, pp, nn, lane);
        applyRy<6>(sr, si, cc, pp, nn, lane);
        applyRy<7>(sr, si, cc, pp, nn, lane);
        // phase diagonal
#pragma unroll
        for (int j = 0; j < 8; j++) {
            int d = POPC[j];
            u64 nr = f2fma(px[d], sr[j], f2mul(pyn[d], si[j]));
            u64 ni = f2fma(px[d], si[j], f2mul(pyp[d], sr[j]));
            sr[j] = nr; si[j] = ni;
        }
        ring_layer(sr, si, lane);
    }

    // ---- save psi0 to shared ----
    u64* myP0 = &shP0[warp * 512 + lane];
#pragma unroll
    for (int j = 0; j < 8; j++) {
        myP0[j * 32] = sr[j];
        myP0[(j + 8) * 32] = si[j];
    }

    u64 featp[6];

    runBranch<0>(sr, si, &shCR[0],  &shU3[0],   lane, featp[0], featp[1]);
#pragma unroll
    for (int j = 0; j < 8; j++) { sr[j] = myP0[j * 32]; si[j] = myP0[(j + 8) * 32]; }
    runBranch<1>(sr, si, &shCR[30], &shU3[72],  lane, featp[2], featp[3]);
#pragma unroll
    for (int j = 0; j < 8; j++) { sr[j] = myP0[j * 32]; si[j] = myP0[(j + 8) * 32]; }
    runBranch<2>(sr, si, &shCR[60], &shU3[144], lane, featp[4], featp[5]);

    // ---- MLP: lane 0 -> element A, lane 1 -> element B ----
    if (lane < 2) {
        float feats[6];
#pragma unroll
        for (int f = 0; f < 6; f++) {
            float x, y; upk(featp[f], x, y);
            feats[f] = (lane == 0) ? x : y;
        }
        float h[12];
#pragma unroll
        for (int k = 0; k < 12; k++) {
            float a = shB1[k];
#pragma unroll
            for (int f = 0; f < 6; f++) a += shW1[k * 6 + f] * feats[f];
            h[k] = tanhf(a);
        }
        float o = shB2;
#pragma unroll
        for (int k = 0; k < 12; k++) o += shW2[k] * h[k];
        int e = e0 + lane;
        if (e < B) out[e] = 1.f / (1.f + expf(-o));
    }
}

extern "C" void kernel_launch(void* const* d_in, const int* in_sizes, int n_in,
                              void* d_out, int out_size) {
    const float* theta    = (const float*)d_in[0];
    const float* phi      = (const float*)d_in[1];
    const float* angles_x = (const float*)d_in[2];
    const float* angles_y = (const float*)d_in[3];
    const float* angles_z = (const float*)d_in[4];
    const float* u3_x     = (const float*)d_in[5];
    const float* u3_y     = (const float*)d_in[6];
    const float* u3_z     = (const float*)d_in[7];
    const float* W1       = (const float*)d_in[8];
    const float* b1       = (const float*)d_in[9];
    const float* W2       = (const float*)d_in[10];
    const float* b2       = (const float*)d_in[11];
    float* out = (float*)d_out;

    int B = in_sizes[0];
    int blocks = (B + 15) / 16;   // 8 warps/block, 2 elements/warp
    qcnn_kernel<<<blocks, 256>>>(theta, phi, angles_x, angles_y, angles_z,
                                 u3_x, u3_y, u3_z, W1, b1, W2, b2, out, B);
}

// round 10
// speedup vs baseline: 1.2051x; 1.2051x over previous
#include <cuda_runtime.h>
#include <cuda_bf16.h>

#define FULLMASK 0xffffffffu
typedef unsigned long long u64;

// One element per warp. State: ar[4], ai[4] (u64 each).
//   u64 halves: .x = amp(q7=0), .y = amp(q7=1)   [re in ar, im in ai]
//   register index k: bit0 = q3, bit1 = q5
//   lane bits L0..L4 = q0,q1,q2,q4,q6
// Position codes: 0 = k0(q3), 1 = k1(q5), 2 = HALF(q7), 3..7 = lane L0..L4.

__device__ __forceinline__ u64 pk(float lo, float hi) {
    u64 r; asm("mov.b64 %0, {%1, %2};" : "=l"(r) : "f"(lo), "f"(hi)); return r;
}
__device__ __forceinline__ void upk(u64 v, float& x, float& y) {
    asm("mov.b64 {%0, %1}, %2;" : "=f"(x), "=f"(y) : "l"(v));
}
__device__ __forceinline__ u64 f2mul(u64 a, u64 b) {
    u64 r; asm("mul.rn.f32x2 %0, %1, %2;" : "=l"(r) : "l"(a), "l"(b)); return r;
}
__device__ __forceinline__ u64 f2fma(u64 a, u64 b, u64 c) {
    u64 r; asm("fma.rn.f32x2 %0, %1, %2, %3;" : "=l"(r) : "l"(a), "l"(b), "l"(c)); return r;
}
__device__ __forceinline__ u64 f2add(u64 a, u64 b) {
    u64 r; asm("add.rn.f32x2 %0, %1, %2;" : "=l"(r) : "l"(a), "l"(b)); return r;
}
__device__ __forceinline__ u64 swp(u64 v) { float x, y; upk(v, x, y); return pk(y, x); }
__device__ __forceinline__ u64 shx64(u64 v, int m) { return __shfl_xor_sync(FULLMASK, v, m); }

// ---- Ry(theta) on position T. cc=(c,c) pp=(s,s) nn=(-s,-s) hyn=(-s,s) ----
template <int T>
__device__ __forceinline__ void applyRy(u64 ar[4], u64 ai[4], u64 cc, u64 pp, u64 nn, u64 hyn, int lane) {
    if constexpr (T == 0 || T == 1) {
        constexpr int step = (T == 0) ? 1 : 2;
#pragma unroll
        for (int p = 0; p < 2; p++) {
            const int a = (T == 0) ? p * 2 : p;
            const int b = a + step;
            u64 xar = ar[a], xbr = ar[b], xai = ai[a], xbi = ai[b];
            ar[a] = f2fma(cc, xar, f2mul(nn, xbr));
            ai[a] = f2fma(cc, xai, f2mul(nn, xbi));
            ar[b] = f2fma(cc, xbr, f2mul(pp, xar));
            ai[b] = f2fma(cc, xbi, f2mul(pp, xai));
        }
    } else if constexpr (T == 2) {
#pragma unroll
        for (int k = 0; k < 4; k++) {
            ar[k] = f2fma(cc, ar[k], f2mul(hyn, swp(ar[k])));
            ai[k] = f2fma(cc, ai[k], f2mul(hyn, swp(ai[k])));
        }
    } else {
        constexpr int lb = 1 << (T - 3);
        u64 sg = (lane & lb) ? pp : nn;
#pragma unroll
        for (int k = 0; k < 4; k++) {
            u64 orr = shx64(ar[k], lb);
            u64 oii = shx64(ai[k], lb);
            ar[k] = f2fma(cc, ar[k], f2mul(sg, orr));
            ai[k] = f2fma(cc, ai[k], f2mul(sg, oii));
        }
    }
}

// ---- controlled rotation. K=0 rx, 1 ry, 2 rz. G: cc, ps, ns, pm=(s,-s), mp=(-s,s) ----
template <int K, int C, int T>
__device__ __forceinline__ void applyCR(u64 ar[4], u64 ai[4], const u64* __restrict__ G, int lane) {
    u64 cc = G[0], ps = G[1], ns = G[2];
    bool lc = (C >= 3) ? (((lane >> (C - 3)) & 1) != 0) : true;
    if constexpr (K == 2) {
        u64 pm = G[3], mp = G[4];
#pragma unroll
        for (int k = 0; k < 4; k++) {
            if constexpr (C == 0) { if (!(k & 1)) continue; }
            if constexpr (C == 1) { if (!(k & 2)) continue; }
            u64 Sr, Si;
            if constexpr (T >= 3) {
                bool tb = ((lane >> (T - 3)) & 1) != 0;
                Sr = tb ? ns : ps; Si = tb ? ps : ns;
            } else if constexpr (T == 2) { Sr = pm; Si = mp; }
            else if constexpr (T == 0) { Sr = (k & 1) ? ns : ps; Si = (k & 1) ? ps : ns; }
            else { Sr = (k & 2) ? ns : ps; Si = (k & 2) ? ps : ns; }
            u64 nr = f2fma(cc, ar[k], f2mul(Sr, ai[k]));
            u64 ni = f2fma(cc, ai[k], f2mul(Si, ar[k]));
            if (lc) { ar[k] = nr; ai[k] = ni; }
        }
    } else if constexpr (T >= 3) {
        constexpr int lb = 1 << (T - 3);
        u64 sg = (lane & lb) ? ps : ns;
#pragma unroll
        for (int k = 0; k < 4; k++) {
            if constexpr (C == 0) { if (!(k & 1)) continue; }
            if constexpr (C == 1) { if (!(k & 2)) continue; }
            u64 orr = shx64(ar[k], lb);
            u64 oii = shx64(ai[k], lb);
            u64 nr, ni;
            if constexpr (K == 0) {
                nr = f2fma(cc, ar[k], f2mul(ps, oii));
                ni = f2fma(cc, ai[k], f2mul(ns, orr));
            } else {
                nr = f2fma(cc, ar[k], f2mul(sg, orr));
                ni = f2fma(cc, ai[k], f2mul(sg, oii));
            }
            if (lc) { ar[k] = nr; ai[k] = ni; }
        }
    } else if constexpr (T == 2) {
        u64 mp = G[4];
#pragma unroll
        for (int k = 0; k < 4; k++) {
            if constexpr (C == 0) { if (!(k & 1)) continue; }
            if constexpr (C == 1) { if (!(k & 2)) continue; }
            u64 nr, ni;
            if constexpr (K == 0) {
                nr = f2fma(cc, ar[k], f2mul(ps, swp(ai[k])));
                ni = f2fma(cc, ai[k], f2mul(ns, swp(ar[k])));
            } else {
                nr = f2fma(cc, ar[k], f2mul(mp, swp(ar[k])));
                ni = f2fma(cc, ai[k], f2mul(mp, swp(ai[k])));
            }
            if (lc) { ar[k] = nr; ai[k] = ni; }
        }
    } else {
        constexpr int step = (T == 0) ? 1 : 2;
#pragma unroll
        for (int p = 0; p < 2; p++) {
            const int a = (T == 0) ? p * 2 : p;
            const int b = a + step;
            if constexpr (C == 0) { if (!(a & 1)) continue; }
            if constexpr (C == 1) { if (!(a & 2)) continue; }
            u64 nar, nai, nbr, nbi;
            if constexpr (K == 0) {
                nar = f2fma(cc, ar[a], f2mul(ps, ai[b]));
                nai = f2fma(cc, ai[a], f2mul(ns, ar[b]));
                nbr = f2fma(cc, ar[b], f2mul(ps, ai[a]));
                nbi = f2fma(cc, ai[b], f2mul(ns, ar[a]));
            } else {
                nar = f2fma(cc, ar[a], f2mul(ns, ar[b]));
                nai = f2fma(cc, ai[a], f2mul(ns, ai[b]));
                nbr = f2fma(cc, ar[b], f2mul(ps, ar[a]));
                nbi = f2fma(cc, ai[b], f2mul(ps, ai[a]));
            }
            if (lc) { ar[a] = nar; ai[a] = nai; ar[b] = nbr; ai[b] = nbi; }
        }
    }
}

// ---- u3 lane target (lb): U[0..5] row_lo {Ar,Ai,nAi,Br,Bi,nBi}, U[6..11] row_hi ----
template <int lb>
__device__ __forceinline__ void applyU3lane(u64 ar[4], u64 ai[4], const u64* __restrict__ U, int lane) {
    const u64* R = U + ((lane & lb) ? 6 : 0);
    u64 Ar = R[0], Ai = R[1], nAi = R[2], Br = R[3], Bi = R[4], nBi = R[5];
#pragma unroll
    for (int k = 0; k < 4; k++) {
        u64 orr = shx64(ar[k], lb);
        u64 oii = shx64(ai[k], lb);
        u64 nr = f2fma(Ar, ar[k], f2fma(nAi, ai[k], f2fma(Br, orr, f2mul(nBi, oii))));
        u64 ni = f2fma(Ar, ai[k], f2fma(Ai, ar[k], f2fma(Br, oii, f2mul(Bi, orr))));
        ar[k] = nr; ai[k] = ni;
    }
}

// ---- u3 register target T (0:k0, 1:k1): U {u00r,u01r,u01i,nu01i,u10r,u10i,nu10i,u11r,u11i,nu11i} ----
template <int T>
__device__ __forceinline__ void applyU3reg(u64 ar[4], u64 ai[4], const u64* __restrict__ U) {
    constexpr int step = (T == 0) ? 1 : 2;
#pragma unroll
    for (int p = 0; p < 2; p++) {
        const int a = (T == 0) ? p * 2 : p;
        const int b = a + step;
        u64 ra = ar[a], ia = ai[a], rb = ar[b], ib = ai[b];
        ar[a] = f2fma(U[0], ra, f2fma(U[1], rb, f2mul(U[3], ib)));
        ai[a] = f2fma(U[0], ia, f2fma(U[1], ib, f2mul(U[2], rb)));
        ar[b] = f2fma(U[7], rb, f2fma(U[9], ib, f2fma(U[4], ra, f2mul(U[6], ia))));
        ai[b] = f2fma(U[7], ib, f2fma(U[8], rb, f2fma(U[4], ia, f2mul(U[5], ra))));
    }
}

// ---- u3 half target (q7): U {D0,D1,nD1,D2,D3,nD3} ----
__device__ __forceinline__ void applyU3half(u64 ar[4], u64 ai[4], const u64* __restrict__ U) {
    u64 D0 = U[0], D1 = U[1], nD1 = U[2], D2 = U[3], D3 = U[4], nD3 = U[5];
#pragma unroll
    for (int k = 0; k < 4; k++) {
        u64 swr = swp(ar[k]), swi = swp(ai[k]);
        u64 nr = f2fma(D0, ar[k], f2fma(D1, ai[k], f2fma(D2, swr, f2mul(D3, swi))));
        u64 ni = f2fma(D0, ai[k], f2fma(nD1, ar[k], f2fma(D2, swi, f2mul(nD3, swr))));
        ar[k] = nr; ai[k] = ni;
    }
}

// ---- CNOT ring: (q0,q1)(q1,q2)(q2,q3)(q3,q4)(q4,q5)(q5,q6)(q6,q7)(q7,q0) ----
__device__ __forceinline__ void ring_layer(u64 ar[4], u64 ai[4], int lane) {
    // (q0,q1)+(q1,q2): fused lane permutation gather
    {
        int src = lane ^ (((lane >> 1) & 1) << 2) ^ ((lane & 1) << 1);
#pragma unroll
        for (int k = 0; k < 4; k++) {
            ar[k] = __shfl_sync(FULLMASK, ar[k], src);
            ai[k] = __shfl_sync(FULLMASK, ai[k], src);
        }
    }
    // (q2,q3): ctrl L2 (lane&4), target k0: swap reg pairs
    if (lane & 4) {
        u64 t;
        t = ar[0]; ar[0] = ar[1]; ar[1] = t;
        t = ar[2]; ar[2] = ar[3]; ar[3] = t;
        t = ai[0]; ai[0] = ai[1]; ai[1] = t;
        t = ai[2]; ai[2] = ai[3]; ai[3] = t;
    }
    // (q3,q4): ctrl k0, target L3 (xor 8): only k=1,3
    ar[1] = shx64(ar[1], 8); ai[1] = shx64(ai[1], 8);
    ar[3] = shx64(ar[3], 8); ai[3] = shx64(ai[3], 8);
    // (q4,q5): ctrl L3 (lane&8), target k1
    if (lane & 8) {
        u64 t;
        t = ar[0]; ar[0] = ar[2]; ar[2] = t;
        t = ar[1]; ar[1] = ar[3]; ar[3] = t;
        t = ai[0]; ai[0] = ai[2]; ai[2] = t;
        t = ai[1]; ai[1] = ai[3]; ai[3] = t;
    }
    // (q5,q6): ctrl k1, target L4 (xor 16): only k=2,3
    ar[2] = shx64(ar[2], 16); ai[2] = shx64(ai[2], 16);
    ar[3] = shx64(ar[3], 16); ai[3] = shx64(ai[3], 16);
    // (q6,q7): ctrl L4 (lane&16), target half
    if (lane & 16) {
#pragma unroll
        for (int k = 0; k < 4; k++) { ar[k] = swp(ar[k]); ai[k] = swp(ai[k]); }
    }
    // (q7,q0): ctrl half (q7=1 -> .y), target L0: shuffle only .y halves by xor 1
#pragma unroll
    for (int k = 0; k < 4; k++) {
        float x, y;
        upk(ar[k], x, y);
        y = __shfl_xor_sync(FULLMASK, y, 1);
        ar[k] = pk(x, y);
        upk(ai[k], x, y);
        y = __shfl_xor_sync(FULLMASK, y, 1);
        ai[k] = pk(x, y);
    }
}

template <int K>
__device__ __forceinline__ void runBranch(u64 ar[4], u64 ai[4],
                                          const u64* __restrict__ CR,
                                          const u64* __restrict__ UM,
                                          int lane, float& e3, float& e7) {
#define CRG(i, C, T) applyCR<K, C, T>(ar, ai, CR + (i) * 5, lane);
    // PAIRS_A: (0,1)(2,3)(4,5)(6,7)(1,2)(3,4)(5,6) -> codes
    CRG(0, 3, 4)   // q0->q1: L0 ctrl, L1 target
    CRG(1, 5, 0)   // q2->q3
    CRG(2, 6, 1)   // q4->q5
    CRG(3, 7, 2)   // q6->q7
    CRG(4, 4, 5)   // q1->q2
    CRG(5, 0, 6)   // q3->q4
    CRG(6, 1, 7)   // q5->q6
    // u3 wires 1,3,5,7
    applyU3lane<2>(ar, ai, UM + 0 * 12, lane);   // q1 = L1
    applyU3reg<0>(ar, ai, UM + 1 * 12);          // q3
    applyU3reg<1>(ar, ai, UM + 2 * 12);          // q5
    applyU3half(ar, ai, UM + 3 * 12);            // q7
    // PAIRS_B: (1,3)(5,7)(3,5)
    CRG(7, 4, 0)   // q1->q3
    CRG(8, 1, 2)   // q5->q7
    CRG(9, 0, 1)   // q3->q5
    // u3 wires 3,7
    applyU3reg<0>(ar, ai, UM + 4 * 12);
    applyU3half(ar, ai, UM + 5 * 12);
#undef CRG

    // expz(q3) sign = k bit0; expz(q7) sign = half
    u64 q0 = f2fma(ar[0], ar[0], f2mul(ai[0], ai[0]));
    u64 q1 = f2fma(ar[1], ar[1], f2mul(ai[1], ai[1]));
    u64 q2 = f2fma(ar[2], ar[2], f2mul(ai[2], ai[2]));
    u64 q3 = f2fma(ar[3], ar[3], f2mul(ai[3], ai[3]));
    u64 s02 = f2add(q0, q2);
    u64 s13 = f2add(q1, q3);
    float a, b, c, d;
    upk(s02, a, b); upk(s13, c, d);
    float le3 = (a + b) - (c + d);
    float le7 = (a + c) - (b + d);
    u64 e = pk(le3, le7);
#pragma unroll
    for (int o = 16; o > 0; o >>= 1) e = f2add(e, shx64(e, o));
    upk(e, e3, e7);
}

__global__ __launch_bounds__(256) void qcnn_kernel(
    const float* __restrict__ theta, const float* __restrict__ phi,
    const float* __restrict__ angles_x, const float* __restrict__ angles_y,
    const float* __restrict__ angles_z,
    const float* __restrict__ u3_x, const float* __restrict__ u3_y,
    const float* __restrict__ u3_z,
    const float* __restrict__ W1, const float* __restrict__ b1,
    const float* __restrict__ W2, const float* __restrict__ b2,
    float* __restrict__ out, int B)
{
    __shared__ u64 shCR[3 * 10 * 5];
    __shared__ u64 shU3[3 * 6 * 12];
    __shared__ u64 shP0[8 * 256];     // [warp][8 slots][32 lanes]
    __shared__ float shW1[72], shB1[12], shW2[12];
    __shared__ float shB2;

    int tid = threadIdx.x;
    if (tid < 30) {
        int b = tid / 10, i = tid % 10;
        const float* ang = (b == 0) ? angles_x : (b == 1) ? angles_y : angles_z;
        float sn, c;
        sincosf(0.5f * ang[i], &sn, &c);
        u64* g = &shCR[tid * 5];
        g[0] = pk(c, c);
        g[1] = pk(sn, sn);
        g[2] = pk(-sn, -sn);
        g[3] = pk(sn, -sn);
        g[4] = pk(-sn, sn);
    }
    if (tid >= 32 && tid < 50) {
        int k = tid - 32;
        int b = k / 6, i = k % 6;
        const float* up = ((b == 0) ? u3_x : (b == 1) ? u3_y : u3_z) + i * 3;
        float th = up[0], ph = up[1], lm = up[2];
        float sn, c;    sincosf(0.5f * th, &sn, &c);
        float sl, cl;   sincosf(lm, &sl, &cl);
        float sp, cp;   sincosf(ph, &sp, &cp);
        float spl, cpl; sincosf(ph + lm, &spl, &cpl);
        float u01r = -cl * sn, u01i = -sl * sn;
        float u10r = cp * sn,  u10i = sp * sn;
        float u11r = cpl * c,  u11i = spl * c;
        u64* g = &shU3[k * 12];
        if (i == 0) {
            // lane-target layout
            g[0] = pk(c, c);        g[1] = pk(0.f, 0.f);      g[2] = pk(0.f, 0.f);
            g[3] = pk(u01r, u01r);  g[4] = pk(u01i, u01i);    g[5] = pk(-u01i, -u01i);
            g[6] = pk(u11r, u11r);  g[7] = pk(u11i, u11i);    g[8] = pk(-u11i, -u11i);
            g[9] = pk(u10r, u10r);  g[10] = pk(u10i, u10i);   g[11] = pk(-u10i, -u10i);
        } else if (i == 3 || i == 5) {
            // half-target layout: D0,D1,nD1,D2,D3,nD3
            g[0] = pk(c, u11r);
            g[1] = pk(0.f, -u11i);
            g[2] = pk(0.f, u11i);
            g[3] = pk(u01r, u10r);
            g[4] = pk(-u01i, -u10i);
            g[5] = pk(u01i, u10i);
        } else {
            // register-target layout
            g[0] = pk(c, c);
            g[1] = pk(u01r, u01r);  g[2] = pk(u01i, u01i);   g[3] = pk(-u01i, -u01i);
            g[4] = pk(u10r, u10r);  g[5] = pk(u10i, u10i);   g[6] = pk(-u10i, -u10i);
            g[7] = pk(u11r, u11r);  g[8] = pk(u11i, u11i);   g[9] = pk(-u11i, -u11i);
        }
    }
    if (tid >= 64 && tid < 136)  shW1[tid - 64] = W1[tid - 64];
    if (tid >= 136 && tid < 148) shB1[tid - 136] = b1[tid - 136];
    if (tid >= 148 && tid < 160) shW2[tid - 148] = W2[tid - 148];
    if (tid == 160) shB2 = b2[0];
    __syncthreads();

    int warp = tid >> 5;
    int lane = tid & 31;
    int batch = blockIdx.x * 8 + warp;
    if (batch >= B) return;

    float th = theta[batch];
    float ph = phi[batch];

    float sy, cy;
    sincosf(0.5f * th, &sy, &cy);
    u64 cc = pk(cy, cy), pp = pk(sy, sy), nn = pk(-sy, -sy), hyn = pk(-sy, sy);

    // phase tables: pxl[d]=cos(ph*(pl+d-4)), pyl[d]=sin, d=0..3 (d = popc(k)+q7)
    int pl = __popc(lane);
    float c1x, c1y; sincosf(ph, &c1y, &c1x);
    float pxl[4], pyl[4];
    sincosf(ph * (float)(pl - 4), &pyl[0], &pxl[0]);
#pragma unroll
    for (int d = 0; d < 3; d++) {
        pxl[d + 1] = pxl[d] * c1x - pyl[d] * c1y;
        pyl[d + 1] = pxl[d] * c1y + pyl[d] * c1x;
    }
    // packed phase consts for cycle use: m = popc(k) in {0,1,2}
    u64 PX[3], PYP[3], PYN[3];
#pragma unroll
    for (int m = 0; m < 3; m++) {
        PX[m]  = pk(pxl[m], pxl[m + 1]);
        PYP[m] = pk(pyl[m], pyl[m + 1]);
        PYN[m] = pk(-pyl[m], -pyl[m + 1]);
    }

    // ---- cycle 1: closed-form product state ----
    u64 ar[4], ai[4];
    {
        float base = 1.f;
#pragma unroll
        for (int kk = 0; kk < 5; kk++) base *= ((lane >> kk) & 1) ? sy : cy;
        float g0 = cy * cy * cy;
        float g1 = cy * cy * sy;
        float g2 = cy * sy * sy;
        float g3 = sy * sy * sy;
        float gt[4] = {g0, g1, g2, g3};
        const int DK[4] = {0, 1, 1, 2};
#pragma unroll
        for (int k = 0; k < 4; k++) {
            int d = DK[k];
            float wlo = base * gt[d], whi = base * gt[d + 1];
            ar[k] = pk(wlo * pxl[d], whi * pxl[d + 1]);
            ai[k] = pk(wlo * pyl[d], whi * pyl[d + 1]);
        }
    }
    ring_layer(ar, ai, lane);

    // ---- cycles 2..4 ----
#pragma unroll 1
    for (int cyc = 0; cyc < 3; cyc++) {
        applyRy<0>(ar, ai, cc, pp, nn, hyn, lane);
        applyRy<3>(ar, ai, cc, pp, nn, hyn, lane);
        applyRy<1>(ar, ai, cc, pp, nn, hyn, lane);
        applyRy<4>(ar, ai, cc, pp, nn, hyn, lane);
        applyRy<2>(ar, ai, cc, pp, nn, hyn, lane);
        applyRy<5>(ar, ai, cc, pp, nn, hyn, lane);
        applyRy<6>(ar, ai, cc, pp, nn, hyn, lane);
        applyRy<7>(ar, ai, cc, pp, nn, hyn, lane);
        // combined Rz diagonal
        {
            const int DK[4] = {0, 1, 1, 2};
#pragma unroll
            for (int k = 0; k < 4; k++) {
                int m = DK[k];
                u64 nr = f2fma(PX[m], ar[k], f2mul(PYN[m], ai[k]));
                u64 ni = f2fma(PX[m], ai[k], f2mul(PYP[m], ar[k]));
                ar[k] = nr; ai[k] = ni;
            }
        }
        ring_layer(ar, ai, lane);
    }

    // ---- psi0 snapshot ----
    u64* myP0 = &shP0[warp * 256 + lane];
#pragma unroll
    for (int k = 0; k < 4; k++) {
        myP0[k * 32] = ar[k];
        myP0[(k + 4) * 32] = ai[k];
    }

    float feats[6];

    runBranch<0>(ar, ai, &shCR[0],   &shU3[0],   lane, feats[0], feats[1]);
#pragma unroll
    for (int k = 0; k < 4; k++) { ar[k] = myP0[k * 32]; ai[k] = myP0[(k + 4) * 32]; }
    runBranch<1>(ar, ai, &shCR[50],  &shU3[72],  lane, feats[2], feats[3]);
#pragma unroll
    for (int k = 0; k < 4; k++) { ar[k] = myP0[k * 32]; ai[k] = myP0[(k + 4) * 32]; }
    runBranch<2>(ar, ai, &shCR[100], &shU3[144], lane, feats[4], feats[5]);

    // ---- MLP (lane 0 only) ----
    if (lane == 0) {
        float h[12];
#pragma unroll
        for (int k = 0; k < 12; k++) {
            float a = shB1[k];
#pragma unroll
            for (int f = 0; f < 6; f++) a += shW1[k * 6 + f] * feats[f];
            h[k] = tanhf(a);
        }
        float o = shB2;
#pragma unroll
        for (int k = 0; k < 12; k++) o += shW2[k] * h[k];
        out[batch] = 1.f / (1.f + expf(-o));
    }
}

extern "C" void kernel_launch(void* const* d_in, const int* in_sizes, int n_in,
                              void* d_out, int out_size) {
    const float* theta    = (const float*)d_in[0];
    const float* phi      = (const float*)d_in[1];
    const float* angles_x = (const float*)d_in[2];
    const float* angles_y = (const float*)d_in[3];
    const float* angles_z = (const float*)d_in[4];
    const float* u3_x     = (const float*)d_in[5];
    const float* u3_y     = (const float*)d_in[6];
    const float* u3_z     = (const float*)d_in[7];
    const float* W1       = (const float*)d_in[8];
    const float* b1       = (const float*)d_in[9];
    const float* W2       = (const float*)d_in[10];
    const float* b2       = (const float*)d_in[11];
    float* out = (float*)d_out;

    int B = in_sizes[0];
    int blocks = (B + 7) / 8;
    qcnn_kernel<<<blocks, 256>>>(theta, phi, angles_x, angles_y, angles_z,
                                 u3_x, u3_y, u3_z, W1, b1, W2, b2, out, B);
}

// round 11
// speedup vs baseline: 1.2939x; 1.0737x over previous
#include <cuda_runtime.h>
#include <cuda_bf16.h>

#define FULLMASK 0xffffffffu
typedef unsigned long long u64;

// Qubit -> amplitude-index-bit mapping (layout A, = R4 champion):
//   q3->bit0, q5->bit1, q7->bit2  (register bits: j index 0..7)
//   q0->L0, q1->L1, q2->L2, q4->L3, q6->L4  (lane bits)
// amp index = (lane << 3) | j ; amplitude = packed (re, im) in one u64.
// Init cycles use a per-warp smem transpose to layout B (regs = q0,q1,q2;
// lanes = q3,q5,q7,q4,q6) so all 8 Ry gates except q4,q6 are register-local.
// Memory slot for amp with qubit values x: m(x) = v + 9*jm + 72*u,
//   v = q0+2q1+4q2, jm = q3+2q5+4q7, u = q4+2q6   (bank-optimal, max 287).

__device__ __forceinline__ u64 pk(float lo, float hi) {
    u64 r; asm("mov.b64 %0, {%1, %2};" : "=l"(r) : "f"(lo), "f"(hi)); return r;
}
__device__ __forceinline__ void upk(u64 v, float& x, float& y) {
    asm("mov.b64 {%0, %1}, %2;" : "=f"(x), "=f"(y) : "l"(v));
}
__device__ __forceinline__ u64 f2mul(u64 a, u64 b) {
    u64 r; asm("mul.rn.f32x2 %0, %1, %2;" : "=l"(r) : "l"(a), "l"(b)); return r;
}
__device__ __forceinline__ u64 f2fma(u64 a, u64 b, u64 c) {
    u64 r; asm("fma.rn.f32x2 %0, %1, %2, %3;" : "=l"(r) : "l"(a), "l"(b), "l"(c)); return r;
}
__device__ __forceinline__ u64 swp(u64 v) { float x, y; upk(v, x, y); return pk(y, x); }
__device__ __forceinline__ u64 shx64(u64 v, int m) { return __shfl_xor_sync(FULLMASK, v, m); }
__device__ __forceinline__ u64 shxswp(u64 v, int m) {
    float x, y; upk(v, x, y);
    float sx = __shfl_xor_sync(FULLMASK, x, m);
    float sy = __shfl_xor_sync(FULLMASK, y, m);
    return pk(sy, sx);
}

// ---- Ry on index-bit Tb (register bits 0..2 or lane bits 3..7) ----
template <int Tb>
__device__ __forceinline__ void applyRy(u64 s[8], u64 cc, u64 pp, u64 nn, int lane) {
    if constexpr (Tb < 3) {
        constexpr int m = 1 << Tb;
#pragma unroll
        for (int j = 0; j < 8; j++) {
            if (!(j & m)) {
                u64 a = s[j], b = s[j | m];
                s[j]     = f2fma(cc, a, f2mul(nn, b));
                s[j | m] = f2fma(cc, b, f2mul(pp, a));
            }
        }
    } else {
        constexpr int lb = 1 << (Tb - 3);
        u64 sg = (lane & lb) ? pp : nn;
#pragma unroll
        for (int j = 0; j < 8; j++) {
            u64 o = shx64(s[j], lb);
            s[j] = f2fma(cc, s[j], f2mul(sg, o));
        }
    }
}

// ---- controlled rotation: K=0 rx, K=1 ry, K=2 rz (R4 verbatim) ----
// G[0]=(c,c) G[1]=(s,s) G[2]=(-s,-s) G[3]=(s,-s) G[4]=(-s,s)
template <int K, int Cb, int Tb>
__device__ __forceinline__ void applyCR(u64 s[8], const u64* __restrict__ G, int lane) {
    u64 cc = G[0];
    if constexpr (K == 2) {
        u64 pm = G[3], mp = G[4];
        bool laneT = (Tb >= 3) ? (((lane >> (Tb - 3)) & 1) != 0) : false;
        if constexpr (Cb < 3) {
#pragma unroll
            for (int j = 0; j < 8; j++) {
                if (j & (1 << Cb)) {
                    bool tb = (Tb < 3) ? (((j >> Tb) & 1) != 0) : laneT;
                    u64 f = tb ? mp : pm;
                    s[j] = f2fma(cc, s[j], f2mul(f, swp(s[j])));
                }
            }
        } else {
            bool lc = ((lane >> (Cb - 3)) & 1) != 0;
#pragma unroll
            for (int j = 0; j < 8; j++) {
                bool tb = (Tb < 3) ? (((j >> Tb) & 1) != 0) : laneT;
                u64 f = tb ? mp : pm;
                u64 r = f2fma(cc, s[j], f2mul(f, swp(s[j])));
                if (lc) s[j] = r;
            }
        }
    } else if constexpr (Tb < 3) {
        constexpr int tm = 1 << Tb;
        bool lc = (Cb >= 3) ? (((lane >> (Cb - 3)) & 1) != 0) : false;
#pragma unroll
        for (int j = 0; j < 8; j++) {
            if (!(j & tm) && (Cb >= 3 || ((j >> Cb) & 1))) {
                u64 a = s[j], b = s[j | tm], na, nb;
                if constexpr (K == 0) {   // rx
                    u64 pm = G[3];
                    na = f2fma(cc, a, f2mul(pm, swp(b)));
                    nb = f2fma(cc, b, f2mul(pm, swp(a)));
                } else {                  // ry
                    na = f2fma(cc, a, f2mul(G[2], b));
                    nb = f2fma(cc, b, f2mul(G[1], a));
                }
                if constexpr (Cb < 3) { s[j] = na; s[j | tm] = nb; }
                else { if (lc) { s[j] = na; s[j | tm] = nb; } }
            }
        }
    } else {
        constexpr int lb = 1 << (Tb - 3);
        u64 sg = (lane & lb) ? G[1] : G[2];
        if constexpr (Cb < 3) {
#pragma unroll
            for (int j = 0; j < 8; j++) {
                if (j & (1 << Cb)) {
                    if constexpr (K == 0) {
                        u64 os = shxswp(s[j], lb);
                        s[j] = f2fma(cc, s[j], f2mul(G[3], os));
                    } else {
                        u64 o = shx64(s[j], lb);
                        s[j] = f2fma(cc, s[j], f2mul(sg, o));
                    }
                }
            }
        } else {
            bool lc = ((lane >> (Cb - 3)) & 1) != 0;
#pragma unroll
            for (int j = 0; j < 8; j++) {
                u64 r;
                if constexpr (K == 0) r = f2fma(cc, s[j], f2mul(G[3], shxswp(s[j], lb)));
                else                  r = f2fma(cc, s[j], f2mul(sg, shx64(s[j], lb)));
                if (lc) s[j] = r;
            }
        }
    }
}

// ---- general u3 gate (R4 verbatim): uXr=(re,re), uXi=(-im,im) ----
template <int Tb>
__device__ __forceinline__ void applyU3(u64 s[8], const u64* __restrict__ U, int lane) {
    if constexpr (Tb < 3) {
        constexpr int m = 1 << Tb;
#pragma unroll
        for (int j = 0; j < 8; j++) {
            if (!(j & m)) {
                u64 a = s[j], b = s[j | m];
                u64 as = swp(a), bs = swp(b);
                s[j]     = f2fma(U[0], a, f2fma(U[2], b, f2mul(U[3], bs)));
                s[j | m] = f2fma(U[4], a, f2fma(U[5], as, f2fma(U[6], b, f2mul(U[7], bs))));
            }
        }
    } else {
        constexpr int lb = 1 << (Tb - 3);
        bool hi = (lane & lb) != 0;
        u64 Ar = hi ? U[6] : U[0];
        u64 Ai = hi ? U[7] : U[1];
        u64 Br = hi ? U[4] : U[2];
        u64 Bi = hi ? U[5] : U[3];
#pragma unroll
        for (int j = 0; j < 8; j++) {
            float x, y; upk(s[j], x, y);
            float ox = __shfl_xor_sync(FULLMASK, x, lb);
            float oy = __shfl_xor_sync(FULLMASK, y, lb);
            u64 o = pk(ox, oy), os = pk(oy, ox), ss2 = pk(y, x);
            s[j] = f2fma(Ar, s[j], f2fma(Ai, ss2, f2fma(Br, o, f2mul(Bi, os))));
        }
    }
}

template <int K>
__device__ __forceinline__ void runBranch(u64 s[8], const u64* __restrict__ CR,
                                          const u64* __restrict__ UM,
                                          int lane, float& e3, float& e7) {
#define CRG(i, Cb, Tb) applyCR<K, Cb, Tb>(s, CR + (i) * 5, lane);
#define U3G(i, Tb) applyU3<Tb>(s, UM + (i) * 8, lane);
    // PAIRS_A
    CRG(0, 3, 4)  // (0,1)
    CRG(1, 5, 0)  // (2,3)
    CRG(2, 6, 1)  // (4,5)
    CRG(3, 7, 2)  // (6,7)
    CRG(4, 4, 5)  // (1,2)
    CRG(5, 0, 6)  // (3,4)
    CRG(6, 1, 7)  // (5,6)
    // u3 on wires 1,3,5,7 -> bits 4,0,1,2
    U3G(0, 4) U3G(1, 0) U3G(2, 1) U3G(3, 2)
    // PAIRS_B
    CRG(7, 4, 0)  // (1,3)
    CRG(8, 1, 2)  // (5,7)
    CRG(9, 0, 1)  // (3,5)
    // u3 on wires 3,7 -> bits 0,2
    U3G(4, 0) U3G(5, 2)
#undef CRG
#undef U3G

    float q[8];
#pragma unroll
    for (int j = 0; j < 8; j++) {
        float x, y; upk(s[j], x, y);
        q[j] = x * x + y * y;
    }
    e3 = (q[0] - q[1]) + (q[2] - q[3]) + (q[4] - q[5]) + (q[6] - q[7]);
    e7 = (q[0] + q[1]) + (q[2] + q[3]) - (q[4] + q[5]) - (q[6] + q[7]);
#pragma unroll
    for (int o = 16; o > 0; o >>= 1) {
        e3 += __shfl_xor_sync(FULLMASK, e3, o);
        e7 += __shfl_xor_sync(FULLMASK, e7, o);
    }
}

__global__ __launch_bounds__(256) void qcnn_kernel(
    const float* __restrict__ theta, const float* __restrict__ phi,
    const float* __restrict__ angles_x, const float* __restrict__ angles_y,
    const float* __restrict__ angles_z,
    const float* __restrict__ u3_x, const float* __restrict__ u3_y,
    const float* __restrict__ u3_z,
    const float* __restrict__ W1, const float* __restrict__ b1,
    const float* __restrict__ W2, const float* __restrict__ b2,
    float* __restrict__ out, int B)
{
    __shared__ u64 shCR[3 * 10 * 5];
    __shared__ u64 shU3[3 * 6 * 8];
    __shared__ u64 shBuf[8 * 288];     // per-warp transpose buffer (287 slots used)
    __shared__ float shW1[72], shB1[12], shW2[12];
    __shared__ float shB2;

    int tid = threadIdx.x;
    if (tid < 30) {
        int b = tid / 10, i = tid % 10;
        const float* ang = (b == 0) ? angles_x : (b == 1) ? angles_y : angles_z;
        float sn, c;
        sincosf(0.5f * ang[i], &sn, &c);
        u64* g = &shCR[tid * 5];
        g[0] = pk(c, c);
        g[1] = pk(sn, sn);
        g[2] = pk(-sn, -sn);
        g[3] = pk(sn, -sn);
        g[4] = pk(-sn, sn);
    }
    if (tid >= 32 && tid < 50) {
        int k = tid - 32;
        int b = k / 6, i = k % 6;
        const float* up = ((b == 0) ? u3_x : (b == 1) ? u3_y : u3_z) + i * 3;
        float th = up[0], ph = up[1], lm = up[2];
        float sn, c;    sincosf(0.5f * th, &sn, &c);
        float sl, cl;   sincosf(lm, &sl, &cl);
        float sp, cp;   sincosf(ph, &sp, &cp);
        float spl, cpl; sincosf(ph + lm, &spl, &cpl);
        u64* g = &shU3[k * 8];
        g[0] = pk(c, c);                 g[1] = pk(0.f, 0.f);
        g[2] = pk(-cl * sn, -cl * sn);   g[3] = pk(sl * sn, -sl * sn);
        g[4] = pk(cp * sn, cp * sn);     g[5] = pk(-sp * sn, sp * sn);
        g[6] = pk(cpl * c, cpl * c);     g[7] = pk(-spl * c, spl * c);
    }
    if (tid >= 64 && tid < 136)  shW1[tid - 64] = W1[tid - 64];
    if (tid >= 136 && tid < 148) shB1[tid - 136] = b1[tid - 136];
    if (tid >= 148 && tid < 160) shW2[tid - 148] = W2[tid - 148];
    if (tid == 160) shB2 = b2[0];
    __syncthreads();

    int warp = tid >> 5;
    int lane = tid & 31;
    int batch = blockIdx.x * 8 + warp;
    if (batch >= B) return;

    float th = theta[batch];
    float ph = phi[batch];

    float sy, cy;
    sincosf(0.5f * th, &sy, &cy);
    u64 cc = pk(cy, cy), pp = pk(sy, sy), nn = pk(-sy, -sy);

    // Rz-layer diagonal tables: amp *= cis(ph * (popc(idx) - 4))
    float c1x, c1y; sincosf(ph, &c1y, &c1x);
    float cl0x, cl0y; sincosf(ph * (float)(__popc(lane) - 4), &cl0y, &cl0x);
    float px[4], py[4];
    px[0] = cl0x; py[0] = cl0y;
    px[1] = px[0] * c1x - py[0] * c1y; py[1] = px[0] * c1y + py[0] * c1x;
    px[2] = px[1] * c1x - py[1] * c1y; py[2] = px[1] * c1y + py[1] * c1x;
    px[3] = px[2] * c1x - py[2] * c1y; py[3] = px[2] * c1y + py[2] * c1x;
    const int POPC[8] = {0, 1, 1, 2, 1, 2, 2, 3};

    // ---- transpose addressing (per lane, computed once) ----
    u64* buf = &shBuf[warp * 288];
    int low3 = lane & 7, hi2 = (lane >> 3) & 3;
    u64* baseA = buf + low3 + 72 * hi2;       // layout-A store: baseA[9*j]
    u64* baseB = buf + 9 * low3 + 72 * hi2;   // layout-B load/store: baseB[j']
    int l0 = lane & 1, l1 = (lane >> 1) & 1, l2 = (lane >> 2) & 1;
    int l3 = (lane >> 3) & 1, l4 = (lane >> 4) & 1;
    // ring-folded layout-A load addresses: read m(A^-1 y) for my y=(lane,j)
    int adrR[8];
#pragma unroll
    for (int j = 0; j < 8; j++) {
        int j0 = j & 1, j1 = (j >> 1) & 1, j2 = (j >> 2) & 1;
        int x0 = l0 ^ j2, x1 = l1 ^ l0 ^ j2, x2 = l2 ^ l1;
        int x3 = j0 ^ l2, x4 = l3 ^ j0, x5 = j1 ^ l3, x6 = l4 ^ j1, x7 = l4 ^ j2;
        adrR[j] = (x0 + 2 * x1 + 4 * x2) + 9 * (x3 + 2 * x5 + 4 * x7) + 72 * (x4 + 2 * x6);
    }

    // ---- cycle 1: closed-form product state with ring FOLDED (zero shuffles) ----
    // T[p] = cy^(8-p) sy^p cis((p-4) ph), p = popc(A^-1 y); built via z = (sy/cy) cis(ph)
    u64 s[8];
    {
        float tn = sy / cy;                       // cy >= cos(0.5) > 0.87, safe
        float zr = tn * c1x, zi = tn * c1y;
        float cy2 = cy * cy, cy4 = cy2 * cy2, cy8 = cy4 * cy4;
        float c2r = c1x * c1x - c1y * c1y, c2i = 2.f * c1x * c1y;
        float c4r = c2r * c2r - c2i * c2i, c4i = 2.f * c2r * c2i;
        float tr = cy8 * c4r, ti = -cy8 * c4i;    // T[0] = cy^8 cis(-4 ph)
        u64 myT = 0;
#pragma unroll
        for (int p = 0; p < 9; p++) {
            if (lane == p) myT = pk(tr, ti);
            float nr = tr * zr - ti * zi;
            ti = tr * zi + ti * zr;
            tr = nr;
        }
        if (lane < 9) buf[lane] = myT;
        __syncwarp();
        int lb = l0 | ((l1 ^ l0) << 1) | ((l2 ^ l1) << 2) | (l2 << 3) | (l3 * 48) | (l4 * 192);
        const int JB[8] = {0, 24, 96, 120, 131, 155, 227, 251};
#pragma unroll
        for (int j = 0; j < 8; j++) s[j] = buf[__popc(lb ^ JB[j])];
        __syncwarp();
    }

    // ---- cycles 2..4: transpose-based Ry layers, ring folded into load-back ----
#pragma unroll 1
    for (int cyc = 0; cyc < 3; cyc++) {
        // layout A: Ry on q3,q5,q7 (register bits 0,1,2)
        applyRy<0>(s, cc, pp, nn, lane);
        applyRy<1>(s, cc, pp, nn, lane);
        applyRy<2>(s, cc, pp, nn, lane);
        // transpose A -> B
#pragma unroll
        for (int j = 0; j < 8; j++) baseA[9 * j] = s[j];
        __syncwarp();
#pragma unroll
        for (int j = 0; j < 8; j++) s[j] = baseB[j];
        // layout B: Ry on q0,q1,q2 (register bits 0,1,2), q4,q6 (lane bits 3,4)
        applyRy<0>(s, cc, pp, nn, lane);
        applyRy<1>(s, cc, pp, nn, lane);
        applyRy<2>(s, cc, pp, nn, lane);
        applyRy<6>(s, cc, pp, nn, lane);
        applyRy<7>(s, cc, pp, nn, lane);
        // combined Rz diagonal (popc is layout-invariant)
#pragma unroll
        for (int j = 0; j < 8; j++) {
            float x, y; upk(s[j], x, y);
            int d = POPC[j];
            s[j] = pk(px[d] * x - py[d] * y, px[d] * y + py[d] * x);
        }
        // transpose B -> A with ring permutation folded into addresses
#pragma unroll
        for (int j = 0; j < 8; j++) baseB[j] = s[j];
        __syncwarp();
#pragma unroll
        for (int j = 0; j < 8; j++) s[j] = buf[adrR[j]];
        __syncwarp();
    }

    // ---- save psi0 (registers, as in R4 champion) ----
    u64 p0[8];
#pragma unroll
    for (int j = 0; j < 8; j++) p0[j] = s[j];

    float feats[6];

    runBranch<0>(s, &shCR[0],   &shU3[0],  lane, feats[0], feats[1]);
#pragma unroll
    for (int j = 0; j < 8; j++) s[j] = p0[j];
    runBranch<1>(s, &shCR[50],  &shU3[48], lane, feats[2], feats[3]);
#pragma unroll
    for (int j = 0; j < 8; j++) s[j] = p0[j];
    runBranch<2>(s, &shCR[100], &shU3[96], lane, feats[4], feats[5]);

    // ---- MLP (lane 0 only) ----
    if (lane == 0) {
        float h[12];
#pragma unroll
        for (int k = 0; k < 12; k++) {
            float a = shB1[k];
#pragma unroll
            for (int f = 0; f < 6; f++) a += shW1[k * 6 + f] * feats[f];
            h[k] = tanhf(a);
        }
        float o = shB2;
#pragma unroll
        for (int k = 0; k < 12; k++) o += shW2[k] * h[k];
        out[batch] = 1.f / (1.f + expf(-o));
    }
}

extern "C" void kernel_launch(void* const* d_in, const int* in_sizes, int n_in,
                              void* d_out, int out_size) {
    const float* theta    = (const float*)d_in[0];
    const float* phi      = (const float*)d_in[1];
    const float* angles_x = (const float*)d_in[2];
    const float* angles_y = (const float*)d_in[3];
    const float* angles_z = (const float*)d_in[4];
    const float* u3_x     = (const float*)d_in[5];
    const float* u3_y     = (const float*)d_in[6];
    const float* u3_z     = (const float*)d_in[7];
    const float* W1       = (const float*)d_in[8];
    const float* b1       = (const float*)d_in[9];
    const float* W2       = (const float*)d_in[10];
    const float* b2       = (const float*)d_in[11];
    float* out = (float*)d_out;

    int B = in_sizes[0];
    int blocks = (B + 7) / 8;
    qcnn_kernel<<<blocks, 256>>>(theta, phi, angles_x, angles_y, angles_z,
                                 u3_x, u3_y, u3_z, W1, b1, W2, b2, out, B);
}

// round 12
// speedup vs baseline: 1.3151x; 1.0164x over previous
#include <cuda_runtime.h>
#include <cuda_bf16.h>

#define FULLMASK 0xffffffffu
typedef unsigned long long u64;

// Qubit -> amplitude-index-bit mapping (layout A, = R4 champion):
//   q3->bit0, q5->bit1, q7->bit2  (register bits: j index 0..7)
//   q0->L0, q1->L1, q2->L2, q4->L3, q6->L4  (lane bits)
// amp index = (lane << 3) | j ; amplitude = packed (re, im) in one u64.
// Init cycles use a per-warp smem transpose (double-buffered) to layout B.

__device__ __forceinline__ u64 pk(float lo, float hi) {
    u64 r; asm("mov.b64 %0, {%1, %2};" : "=l"(r) : "f"(lo), "f"(hi)); return r;
}
__device__ __forceinline__ void upk(u64 v, float& x, float& y) {
    asm("mov.b64 {%0, %1}, %2;" : "=f"(x), "=f"(y) : "l"(v));
}
__device__ __forceinline__ u64 f2mul(u64 a, u64 b) {
    u64 r; asm("mul.rn.f32x2 %0, %1, %2;" : "=l"(r) : "l"(a), "l"(b)); return r;
}
__device__ __forceinline__ u64 f2fma(u64 a, u64 b, u64 c) {
    u64 r; asm("fma.rn.f32x2 %0, %1, %2, %3;" : "=l"(r) : "l"(a), "l"(b), "l"(c)); return r;
}
__device__ __forceinline__ u64 f2add(u64 a, u64 b) {
    u64 r; asm("add.rn.f32x2 %0, %1, %2;" : "=l"(r) : "l"(a), "l"(b)); return r;
}
__device__ __forceinline__ u64 swp(u64 v) { float x, y; upk(v, x, y); return pk(y, x); }
__device__ __forceinline__ u64 shx64(u64 v, int m) { return __shfl_xor_sync(FULLMASK, v, m); }
__device__ __forceinline__ u64 shxswp(u64 v, int m) {
    float x, y; upk(v, x, y);
    float sx = __shfl_xor_sync(FULLMASK, x, m);
    float sy = __shfl_xor_sync(FULLMASK, y, m);
    return pk(sy, sx);
}

// ---- Ry on index-bit Tb ----
template <int Tb>
__device__ __forceinline__ void applyRy(u64 s[8], u64 cc, u64 pp, u64 nn, int lane) {
    if constexpr (Tb < 3) {
        constexpr int m = 1 << Tb;
#pragma unroll
        for (int j = 0; j < 8; j++) {
            if (!(j & m)) {
                u64 a = s[j], b = s[j | m];
                s[j]     = f2fma(cc, a, f2mul(nn, b));
                s[j | m] = f2fma(cc, b, f2mul(pp, a));
            }
        }
    } else {
        constexpr int lb = 1 << (Tb - 3);
        u64 sg = (lane & lb) ? pp : nn;
#pragma unroll
        for (int j = 0; j < 8; j++) {
            u64 o = shx64(s[j], lb);
            s[j] = f2fma(cc, s[j], f2mul(sg, o));
        }
    }
}

// ---- controlled rotation: K=0 rx, K=1 ry, K=2 rz ----
// G[0]=(c,c) G[1]=(s,s) G[2]=(-s,-s) G[3]=(s,-s) G[4]=(-s,s)
template <int K, int Cb, int Tb>
__device__ __forceinline__ void applyCR(u64 s[8], const u64* __restrict__ G, int lane) {
    u64 cc = G[0];
    if constexpr (K == 2) {
        u64 pm = G[3], mp = G[4];
        bool laneT = (Tb >= 3) ? (((lane >> (Tb - 3)) & 1) != 0) : false;
        if constexpr (Cb < 3) {
#pragma unroll
            for (int j = 0; j < 8; j++) {
                if (j & (1 << Cb)) {
                    bool tb = (Tb < 3) ? (((j >> Tb) & 1) != 0) : laneT;
                    u64 f = tb ? mp : pm;
                    s[j] = f2fma(cc, s[j], f2mul(f, swp(s[j])));
                }
            }
        } else {
            bool lc = ((lane >> (Cb - 3)) & 1) != 0;
#pragma unroll
            for (int j = 0; j < 8; j++) {
                bool tb = (Tb < 3) ? (((j >> Tb) & 1) != 0) : laneT;
                u64 f = tb ? mp : pm;
                u64 r = f2fma(cc, s[j], f2mul(f, swp(s[j])));
                if (lc) s[j] = r;
            }
        }
    } else if constexpr (Tb < 3) {
        constexpr int tm = 1 << Tb;
        bool lc = (Cb >= 3) ? (((lane >> (Cb - 3)) & 1) != 0) : false;
#pragma unroll
        for (int j = 0; j < 8; j++) {
            if (!(j & tm) && (Cb >= 3 || ((j >> Cb) & 1))) {
                u64 a = s[j], b = s[j | tm], na, nb;
                if constexpr (K == 0) {   // rx
                    u64 pm = G[3];
                    na = f2fma(cc, a, f2mul(pm, swp(b)));
                    nb = f2fma(cc, b, f2mul(pm, swp(a)));
                } else {                  // ry
                    na = f2fma(cc, a, f2mul(G[2], b));
                    nb = f2fma(cc, b, f2mul(G[1], a));
                }
                if constexpr (Cb < 3) { s[j] = na; s[j | tm] = nb; }
                else { if (lc) { s[j] = na; s[j | tm] = nb; } }
            }
        }
    } else {
        constexpr int lb = 1 << (Tb - 3);
        u64 sg = (lane & lb) ? G[1] : G[2];
        if constexpr (Cb < 3) {
#pragma unroll
            for (int j = 0; j < 8; j++) {
                if (j & (1 << Cb)) {
                    if constexpr (K == 0) {
                        u64 os = shxswp(s[j], lb);
                        s[j] = f2fma(cc, s[j], f2mul(G[3], os));
                    } else {
                        u64 o = shx64(s[j], lb);
                        s[j] = f2fma(cc, s[j], f2mul(sg, o));
                    }
                }
            }
        } else {
            bool lc = ((lane >> (Cb - 3)) & 1) != 0;
#pragma unroll
            for (int j = 0; j < 8; j++) {
                u64 r;
                if constexpr (K == 0) r = f2fma(cc, s[j], f2mul(G[3], shxswp(s[j], lb)));
                else                  r = f2fma(cc, s[j], f2mul(sg, shx64(s[j], lb)));
                if (lc) s[j] = r;
            }
        }
    }
}

// ---- general u3 gate: uXr=(re,re), uXi=(-im,im) ----
template <int Tb>
__device__ __forceinline__ void applyU3(u64 s[8], const u64* __restrict__ U, int lane) {
    if constexpr (Tb < 3) {
        constexpr int m = 1 << Tb;
#pragma unroll
        for (int j = 0; j < 8; j++) {
            if (!(j & m)) {
                u64 a = s[j], b = s[j | m];
                u64 as = swp(a), bs = swp(b);
                s[j]     = f2fma(U[0], a, f2fma(U[2], b, f2mul(U[3], bs)));
                s[j | m] = f2fma(U[4], a, f2fma(U[5], as, f2fma(U[6], b, f2mul(U[7], bs))));
            }
        }
    } else {
        constexpr int lb = 1 << (Tb - 3);
        bool hi = (lane & lb) != 0;
        u64 Ar = hi ? U[6] : U[0];
        u64 Ai = hi ? U[7] : U[1];
        u64 Br = hi ? U[4] : U[2];
        u64 Bi = hi ? U[5] : U[3];
#pragma unroll
        for (int j = 0; j < 8; j++) {
            float x, y; upk(s[j], x, y);
            float ox = __shfl_xor_sync(FULLMASK, x, lb);
            float oy = __shfl_xor_sync(FULLMASK, y, lb);
            u64 o = pk(ox, oy), os = pk(oy, ox), ss2 = pk(y, x);
            s[j] = f2fma(Ar, s[j], f2fma(Ai, ss2, f2fma(Br, o, f2mul(Bi, os))));
        }
    }
}

// quadratic-form partial: sum over pairs (a, a|bit) of
//   m*(qa - qb) + w2r*Re(psi_a* psi_b) + w2i*Im(psi_a* psi_b)
template <int bit>
__device__ __forceinline__ float quadForm(const u64 s[8], float m, float w2r, float w2i) {
    float acc = 0.f;
#pragma unroll
    for (int j = 0; j < 8; j++) {
        if (!(j & bit)) {
            u64 A = s[j], B = s[j | bit];
            u64 qa = f2mul(A, A), qb = f2mul(B, B);
            u64 rr = f2mul(A, B), ii = f2mul(A, swp(B));
            float qax, qay, qbx, qby, rx, ry, ix, iy;
            upk(qa, qax, qay); upk(qb, qbx, qby);
            upk(rr, rx, ry);   upk(ii, ix, iy);
            acc = fmaf(m, (qax + qay) - (qbx + qby), acc);
            acc = fmaf(w2r, rx + ry, acc);
            acc = fmaf(w2i, ix - iy, acc);
        }
    }
    return acc;
}

template <int K>
__device__ __forceinline__ void runBranch(u64 s[8], const u64* __restrict__ CR,
                                          const u64* __restrict__ UM,
                                          const float* __restrict__ M6,
                                          int lane, float& e3, float& e7) {
#define CRG(i, Cb, Tb) applyCR<K, Cb, Tb>(s, CR + (i) * 5, lane);
#define U3G(i, Tb) applyU3<Tb>(s, UM + (i) * 8, lane);
    // PAIRS_A
    CRG(0, 3, 4)  // (0,1)
    CRG(1, 5, 0)  // (2,3)
    CRG(2, 6, 1)  // (4,5)
    CRG(3, 7, 2)  // (6,7)
    CRG(4, 4, 5)  // (1,2)
    CRG(5, 0, 6)  // (3,4)
    CRG(6, 1, 7)  // (5,6)
    // u3 on wires 1,3,5,7 -> bits 4,0,1,2
    U3G(0, 4) U3G(1, 0) U3G(2, 1) U3G(3, 2)
    // PAIRS_B: (1,3), (5,7)
    CRG(7, 4, 0)
    CRG(8, 1, 2)
    // e7 NOW: remaining ops CR(3,5) [qubits 3,5] and u3(3) commute with any
    // q7 observable; final u3(7) folded into M7 = u3†Z u3.
    float e7l = quadForm<4>(s, M6[3], M6[4], M6[5]);
    // (3,5)
    CRG(9, 0, 1)
    // e3: final u3(3) folded into M3 (u3(7) acts on q7, commutes with M3).
    float e3l = quadForm<1>(s, M6[0], M6[1], M6[2]);
#undef CRG
#undef U3G
    u64 e = pk(e3l, e7l);
#pragma unroll
    for (int o = 16; o > 0; o >>= 1) e = f2add(e, shx64(e, o));
    upk(e, e3, e7);
}

__global__ __launch_bounds__(256) void qcnn_kernel(
    const float* __restrict__ theta, const float* __restrict__ phi,
    const float* __restrict__ angles_x, const float* __restrict__ angles_y,
    const float* __restrict__ angles_z,
    const float* __restrict__ u3_x, const float* __restrict__ u3_y,
    const float* __restrict__ u3_z,
    const float* __restrict__ W1, const float* __restrict__ b1,
    const float* __restrict__ W2, const float* __restrict__ b2,
    float* __restrict__ out, int B)
{
    __shared__ u64 shCR[3 * 10 * 5];
    __shared__ u64 shU3[3 * 6 * 8];
    __shared__ u64 shBuf[8 * 576];     // per-warp DOUBLE transpose buffer
    __shared__ float shM[18];          // per-branch fold consts: m3,w2r3,w2i3,m7,w2r7,w2i7
    __shared__ float shW1[72], shB1[12], shW2[12];
    __shared__ float shB2;

    int tid = threadIdx.x;
    if (tid < 30) {
        int b = tid / 10, i = tid % 10;
        const float* ang = (b == 0) ? angles_x : (b == 1) ? angles_y : angles_z;
        float sn, c;
        sincosf(0.5f * ang[i], &sn, &c);
        u64* g = &shCR[tid * 5];
        g[0] = pk(c, c);
        g[1] = pk(sn, sn);
        g[2] = pk(-sn, -sn);
        g[3] = pk(sn, -sn);
        g[4] = pk(-sn, sn);
    }
    if (tid >= 32 && tid < 50) {
        int k = tid - 32;
        int b = k / 6, i = k % 6;
        const float* up = ((b == 0) ? u3_x : (b == 1) ? u3_y : u3_z) + i * 3;
        float th = up[0], ph = up[1], lm = up[2];
        float sn, c;    sincosf(0.5f * th, &sn, &c);
        float sl, cl;   sincosf(lm, &sl, &cl);
        float sp, cp;   sincosf(ph, &sp, &cp);
        float spl, cpl; sincosf(ph + lm, &spl, &cpl);
        u64* g = &shU3[k * 8];
        g[0] = pk(c, c);                 g[1] = pk(0.f, 0.f);
        g[2] = pk(-cl * sn, -cl * sn);   g[3] = pk(sl * sn, -sl * sn);
        g[4] = pk(cp * sn, cp * sn);     g[5] = pk(-sp * sn, sp * sn);
        g[6] = pk(cpl * c, cpl * c);     g[7] = pk(-spl * c, spl * c);
    }
    if (tid >= 50 && tid < 56) {
        // measurement fold consts: M = u3†Zu3 = [[cos(th), -sin(th)e^{i lm}], ...]
        int k2 = tid - 50;
        int b = k2 / 2, wire = k2 % 2;   // wire 0 -> u3 gate 4 (q3), 1 -> gate 5 (q7)
        const float* up = ((b == 0) ? u3_x : (b == 1) ? u3_y : u3_z) + (4 + wire) * 3;
        float th = up[0], lm = up[2];
        float st, ct; sincosf(th, &st, &ct);
        float sl, cl; sincosf(lm, &sl, &cl);
        float* m = &shM[b * 6 + wire * 3];
        m[0] = ct;
        m[1] = -2.f * st * cl;   // coefficient of Re(psi_a* psi_b)
        m[2] =  2.f * st * sl;   // coefficient of Im(psi_a* psi_b)
    }
    if (tid >= 64 && tid < 136)  shW1[tid - 64] = W1[tid - 64];
    if (tid >= 136 && tid < 148) shB1[tid - 136] = b1[tid - 136];
    if (tid >= 148 && tid < 160) shW2[tid - 148] = W2[tid - 148];
    if (tid == 160) shB2 = b2[0];
    __syncthreads();

    int warp = tid >> 5;
    int lane = tid & 31;
    int batch = blockIdx.x * 8 + warp;
    if (batch >= B) return;

    float th = theta[batch];
    float ph = phi[batch];

    float sy, cy;
    sincosf(0.5f * th, &sy, &cy);
    u64 cc = pk(cy, cy), pp = pk(sy, sy), nn = pk(-sy, -sy);

    // Rz-layer diagonal tables: amp *= cis(ph * (popc(idx) - 4))
    float c1x, c1y; sincosf(ph, &c1y, &c1x);
    float cl0x, cl0y; sincosf(ph * (float)(__popc(lane) - 4), &cl0y, &cl0x);
    float px[4], py[4];
    px[0] = cl0x; py[0] = cl0y;
    px[1] = px[0] * c1x - py[0] * c1y; py[1] = px[0] * c1y + py[0] * c1x;
    px[2] = px[1] * c1x - py[1] * c1y; py[2] = px[1] * c1y + py[1] * c1x;
    px[3] = px[2] * c1x - py[2] * c1y; py[3] = px[2] * c1y + py[2] * c1x;
    const int POPC[8] = {0, 1, 1, 2, 1, 2, 2, 3};

    // ---- transpose addressing ----
    u64* buf0 = &shBuf[warp * 576];
    u64* buf1 = buf0 + 288;
    int low3 = lane & 7, hi2 = (lane >> 3) & 3;
    u64* baseA0 = buf0 + low3 + 72 * hi2;     // layout-A store into buf0
    u64* baseB0 = buf0 + 9 * low3 + 72 * hi2; // layout-B load from buf0
    u64* baseB1 = buf1 + 9 * low3 + 72 * hi2; // layout-B store into buf1
    int l0 = lane & 1, l1 = (lane >> 1) & 1, l2 = (lane >> 2) & 1;
    int l3 = (lane >> 3) & 1, l4 = (lane >> 4) & 1;
    int adrR[8];
#pragma unroll
    for (int j = 0; j < 8; j++) {
        int j0 = j & 1, j1 = (j >> 1) & 1, j2 = (j >> 2) & 1;
        int x0 = l0 ^ j2, x1 = l1 ^ l0 ^ j2, x2 = l2 ^ l1;
        int x3 = j0 ^ l2, x4 = l3 ^ j0, x5 = j1 ^ l3, x6 = l4 ^ j1, x7 = l4 ^ j2;
        adrR[j] = (x0 + 2 * x1 + 4 * x2) + 9 * (x3 + 2 * x5 + 4 * x7) + 72 * (x4 + 2 * x6);
    }

    // ---- cycle 1: closed-form product state with ring folded (zero shuffles) ----
    u64 s[8];
    {
        float tn = sy / cy;
        float zr = tn * c1x, zi = tn * c1y;
        float cy2 = cy * cy, cy4 = cy2 * cy2, cy8 = cy4 * cy4;
        float c2r = c1x * c1x - c1y * c1y, c2i = 2.f * c1x * c1y;
        float c4r = c2r * c2r - c2i * c2i, c4i = 2.f * c2r * c2i;
        float tr = cy8 * c4r, ti = -cy8 * c4i;
        u64 myT = 0;
#pragma unroll
        for (int p = 0; p < 9; p++) {
            if (lane == p) myT = pk(tr, ti);
            float nr = tr * zr - ti * zi;
            ti = tr * zi + ti * zr;
            tr = nr;
        }
        if (lane < 9) buf0[lane] = myT;
        __syncwarp();
        int lb = l0 | ((l1 ^ l0) << 1) | ((l2 ^ l1) << 2) | (l2 << 3) | (l3 * 48) | (l4 * 192);
        const int JB[8] = {0, 24, 96, 120, 131, 155, 227, 251};
#pragma unroll
        for (int j = 0; j < 8; j++) s[j] = buf0[__popc(lb ^ JB[j])];
        __syncwarp();
    }

    // ---- cycles 2..4: transpose-based Ry layers, ring folded into load-back ----
#pragma unroll 1
    for (int cyc = 0; cyc < 3; cyc++) {
        // layout A: Ry on q3,q5,q7 (register bits)
        applyRy<0>(s, cc, pp, nn, lane);
        applyRy<1>(s, cc, pp, nn, lane);
        applyRy<2>(s, cc, pp, nn, lane);
        // transpose A -> B (buf0)
#pragma unroll
        for (int j = 0; j < 8; j++) baseA0[9 * j] = s[j];
        __syncwarp();
#pragma unroll
        for (int j = 0; j < 8; j++) s[j] = baseB0[j];
        // layout B: Ry on q0,q1,q2 (register bits), q4,q6 (lane bits)
        applyRy<0>(s, cc, pp, nn, lane);
        applyRy<1>(s, cc, pp, nn, lane);
        applyRy<2>(s, cc, pp, nn, lane);
        applyRy<6>(s, cc, pp, nn, lane);
        applyRy<7>(s, cc, pp, nn, lane);
        // combined Rz diagonal (popc layout-invariant)
#pragma unroll
        for (int j = 0; j < 8; j++) {
            float x, y; upk(s[j], x, y);
            int d = POPC[j];
            s[j] = pk(px[d] * x - py[d] * y, px[d] * y + py[d] * x);
        }
        // transpose B -> A via buf1 with ring permutation folded
#pragma unroll
        for (int j = 0; j < 8; j++) baseB1[j] = s[j];
        __syncwarp();
#pragma unroll
        for (int j = 0; j < 8; j++) s[j] = buf1[adrR[j]];
        // no trailing syncwarp needed: next A-store targets buf0, and the
        // sync above already ordered all lanes past their buf0 loads.
    }

    // ---- save psi0 ----
    u64 p0[8];
#pragma unroll
    for (int j = 0; j < 8; j++) p0[j] = s[j];

    float feats[6];

    runBranch<0>(s, &shCR[0],   &shU3[0],  &shM[0],  lane, feats[0], feats[1]);
#pragma unroll
    for (int j = 0; j < 8; j++) s[j] = p0[j];
    runBranch<1>(s, &shCR[50],  &shU3[48], &shM[6],  lane, feats[2], feats[3]);
#pragma unroll
    for (int j = 0; j < 8; j++) s[j] = p0[j];
    runBranch<2>(s, &shCR[100], &shU3[96], &shM[12], lane, feats[4], feats[5]);

    // ---- MLP (lane 0 only) ----
    if (lane == 0) {
        float h[12];
#pragma unroll
        for (int k = 0; k < 12; k++) {
            float a = shB1[k];
#pragma unroll
            for (int f = 0; f < 6; f++) a += shW1[k * 6 + f] * feats[f];
            h[k] = tanhf(a);
        }
        float o = shB2;
#pragma unroll
        for (int k = 0; k < 12; k++) o += shW2[k] * h[k];
        out[batch] = 1.f / (1.f + expf(-o));
    }
}

extern "C" void kernel_launch(void* const* d_in, const int* in_sizes, int n_in,
                              void* d_out, int out_size) {
    const float* theta    = (const float*)d_in[0];
    const float* phi      = (const float*)d_in[1];
    const float* angles_x = (const float*)d_in[2];
    const float* angles_y = (const float*)d_in[3];
    const float* angles_z = (const float*)d_in[4];
    const float* u3_x     = (const float*)d_in[5];
    const float* u3_y     = (const float*)d_in[6];
    const float* u3_z     = (const float*)d_in[7];
    const float* W1       = (const float*)d_in[8];
    const float* b1       = (const float*)d_in[9];
    const float* W2       = (const float*)d_in[10];
    const float* b2       = (const float*)d_in[11];
    float* out = (float*)d_out;

    int B = in_sizes[0];
    int blocks = (B + 7) / 8;
    qcnn_kernel<<<blocks, 256>>>(theta, phi, angles_x, angles_y, angles_z,
                                 u3_x, u3_y, u3_z, W1, b1, W2, b2, out, B);
}

// round 13
// speedup vs baseline: 1.3641x; 1.0372x over previous
#include <cuda_runtime.h>
#include <cuda_bf16.h>

#define FULLMASK 0xffffffffu
typedef unsigned long long u64;

// Qubit -> amplitude-index-bit mapping (layout A):
//   q3->bit0, q5->bit1, q7->bit2  (register bits: j index 0..7)
//   q0->L0, q1->L1, q2->L2, q4->L3, q6->L4  (lane bits)
// amp index = (lane << 3) | j ; amplitude = packed (re, im) in one u64.
// Init cycles use a per-warp smem transpose (double-buffered) to layout B.

__device__ __forceinline__ u64 pk(float lo, float hi) {
    u64 r; asm("mov.b64 %0, {%1, %2};" : "=l"(r) : "f"(lo), "f"(hi)); return r;
}
__device__ __forceinline__ void upk(u64 v, float& x, float& y) {
    asm("mov.b64 {%0, %1}, %2;" : "=f"(x), "=f"(y) : "l"(v));
}
__device__ __forceinline__ u64 f2mul(u64 a, u64 b) {
    u64 r; asm("mul.rn.f32x2 %0, %1, %2;" : "=l"(r) : "l"(a), "l"(b)); return r;
}
__device__ __forceinline__ u64 f2fma(u64 a, u64 b, u64 c) {
    u64 r; asm("fma.rn.f32x2 %0, %1, %2, %3;" : "=l"(r) : "l"(a), "l"(b), "l"(c)); return r;
}
__device__ __forceinline__ u64 f2add(u64 a, u64 b) {
    u64 r; asm("add.rn.f32x2 %0, %1, %2;" : "=l"(r) : "l"(a), "l"(b)); return r;
}
__device__ __forceinline__ u64 swp(u64 v) { float x, y; upk(v, x, y); return pk(y, x); }
__device__ __forceinline__ u64 shx64(u64 v, int m) { return __shfl_xor_sync(FULLMASK, v, m); }
__device__ __forceinline__ u64 shxswp(u64 v, int m) {
    float x, y; upk(v, x, y);
    float sx = __shfl_xor_sync(FULLMASK, x, m);
    float sy = __shfl_xor_sync(FULLMASK, y, m);
    return pk(sy, sx);
}

// ---- Ry on index-bit Tb ----
template <int Tb>
__device__ __forceinline__ void applyRy(u64 s[8], u64 cc, u64 pp, u64 nn, int lane) {
    if constexpr (Tb < 3) {
        constexpr int m = 1 << Tb;
#pragma unroll
        for (int j = 0; j < 8; j++) {
            if (!(j & m)) {
                u64 a = s[j], b = s[j | m];
                s[j]     = f2fma(cc, a, f2mul(nn, b));
                s[j | m] = f2fma(cc, b, f2mul(pp, a));
            }
        }
    } else {
        constexpr int lb = 1 << (Tb - 3);
        u64 sg = (lane & lb) ? pp : nn;
#pragma unroll
        for (int j = 0; j < 8; j++) {
            u64 o = shx64(s[j], lb);
            s[j] = f2fma(cc, s[j], f2mul(sg, o));
        }
    }
}

// ---- controlled rotation: K=0 rx, K=1 ry, K=2 rz ----
// G[0]=(c,c) G[1]=(s,s) G[2]=(-s,-s) G[3]=(s,-s) G[4]=(-s,s)
template <int K, int Cb, int Tb>
__device__ __forceinline__ void applyCR(u64 s[8], const u64* __restrict__ G, int lane) {
    u64 cc = G[0];
    if constexpr (K == 2) {
        u64 pm = G[3], mp = G[4];
        bool laneT = (Tb >= 3) ? (((lane >> (Tb - 3)) & 1) != 0) : false;
        if constexpr (Cb < 3) {
#pragma unroll
            for (int j = 0; j < 8; j++) {
                if (j & (1 << Cb)) {
                    bool tb = (Tb < 3) ? (((j >> Tb) & 1) != 0) : laneT;
                    u64 f = tb ? mp : pm;
                    s[j] = f2fma(cc, s[j], f2mul(f, swp(s[j])));
                }
            }
        } else {
            bool lc = ((lane >> (Cb - 3)) & 1) != 0;
#pragma unroll
            for (int j = 0; j < 8; j++) {
                bool tb = (Tb < 3) ? (((j >> Tb) & 1) != 0) : laneT;
                u64 f = tb ? mp : pm;
                u64 r = f2fma(cc, s[j], f2mul(f, swp(s[j])));
                if (lc) s[j] = r;
            }
        }
    } else if constexpr (Tb < 3) {
        constexpr int tm = 1 << Tb;
        bool lc = (Cb >= 3) ? (((lane >> (Cb - 3)) & 1) != 0) : false;
#pragma unroll
        for (int j = 0; j < 8; j++) {
            if (!(j & tm) && (Cb >= 3 || ((j >> Cb) & 1))) {
                u64 a = s[j], b = s[j | tm], na, nb;
                if constexpr (K == 0) {   // rx
                    u64 pm = G[3];
                    na = f2fma(cc, a, f2mul(pm, swp(b)));
                    nb = f2fma(cc, b, f2mul(pm, swp(a)));
                } else {                  // ry
                    na = f2fma(cc, a, f2mul(G[2], b));
                    nb = f2fma(cc, b, f2mul(G[1], a));
                }
                if constexpr (Cb < 3) { s[j] = na; s[j | tm] = nb; }
                else { if (lc) { s[j] = na; s[j | tm] = nb; } }
            }
        }
    } else {
        constexpr int lb = 1 << (Tb - 3);
        u64 sg = (lane & lb) ? G[1] : G[2];
        if constexpr (Cb < 3) {
#pragma unroll
            for (int j = 0; j < 8; j++) {
                if (j & (1 << Cb)) {
                    if constexpr (K == 0) {
                        u64 os = shxswp(s[j], lb);
                        s[j] = f2fma(cc, s[j], f2mul(G[3], os));
                    } else {
                        u64 o = shx64(s[j], lb);
                        s[j] = f2fma(cc, s[j], f2mul(sg, o));
                    }
                }
            }
        } else {
            bool lc = ((lane >> (Cb - 3)) & 1) != 0;
#pragma unroll
            for (int j = 0; j < 8; j++) {
                u64 r;
                if constexpr (K == 0) r = f2fma(cc, s[j], f2mul(G[3], shxswp(s[j], lb)));
                else                  r = f2fma(cc, s[j], f2mul(sg, shx64(s[j], lb)));
                if (lc) s[j] = r;
            }
        }
    }
}

// ---- general u3 gate: uXr=(re,re), uXi=(-im,im) ----
template <int Tb>
__device__ __forceinline__ void applyU3(u64 s[8], const u64* __restrict__ U, int lane) {
    if constexpr (Tb < 3) {
        constexpr int m = 1 << Tb;
#pragma unroll
        for (int j = 0; j < 8; j++) {
            if (!(j & m)) {
                u64 a = s[j], b = s[j | m];
                u64 as = swp(a), bs = swp(b);
                s[j]     = f2fma(U[0], a, f2fma(U[2], b, f2mul(U[3], bs)));
                s[j | m] = f2fma(U[4], a, f2fma(U[5], as, f2fma(U[6], b, f2mul(U[7], bs))));
            }
        }
    } else {
        constexpr int lb = 1 << (Tb - 3);
        bool hi = (lane & lb) != 0;
        u64 Ar = hi ? U[6] : U[0];
        u64 Ai = hi ? U[7] : U[1];
        u64 Br = hi ? U[4] : U[2];
        u64 Bi = hi ? U[5] : U[3];
#pragma unroll
        for (int j = 0; j < 8; j++) {
            float x, y; upk(s[j], x, y);
            float ox = __shfl_xor_sync(FULLMASK, x, lb);
            float oy = __shfl_xor_sync(FULLMASK, y, lb);
            u64 o = pk(ox, oy), os = pk(oy, ox), ss2 = pk(y, x);
            s[j] = f2fma(Ar, s[j], f2fma(Ai, ss2, f2fma(Br, o, f2mul(Bi, os))));
        }
    }
}

// quadratic-form partial over pairs (a, a|bit):
//   m*(qa - qb) + w2r*Re(psi_a* psi_b) + w2i*Im(psi_a* psi_b)
template <int bit>
__device__ __forceinline__ float quadForm(const u64 s[8], float m, float w2r, float w2i) {
    float acc = 0.f;
#pragma unroll
    for (int j = 0; j < 8; j++) {
        if (!(j & bit)) {
            u64 A = s[j], B = s[j | bit];
            u64 qa = f2mul(A, A), qb = f2mul(B, B);
            u64 rr = f2mul(A, B), ii = f2mul(A, swp(B));
            float qax, qay, qbx, qby, rx, ry, ix, iy;
            upk(qa, qax, qay); upk(qb, qbx, qby);
            upk(rr, rx, ry);   upk(ii, ix, iy);
            acc = fmaf(m, (qax + qay) - (qbx + qby), acc);
            acc = fmaf(w2r, rx + ry, acc);
            acc = fmaf(w2i, ix - iy, acc);
        }
    }
    return acc;
}

template <int K>
__device__ __forceinline__ void runBranch(u64 s[8], const u64* __restrict__ CR,
                                          const u64* __restrict__ UM,
                                          const float* __restrict__ M6,
                                          int lane, float& e3, float& e7) {
#define CRG(i, Cb, Tb) applyCR<K, Cb, Tb>(s, CR + (i) * 5, lane);
#define U3G(i, Tb) applyU3<Tb>(s, UM + (i) * 8, lane);
    // PAIRS_A
    CRG(0, 3, 4)  // (0,1)
    CRG(1, 5, 0)  // (2,3)
    CRG(2, 6, 1)  // (4,5)
    CRG(3, 7, 2)  // (6,7)
    CRG(4, 4, 5)  // (1,2)
    CRG(5, 0, 6)  // (3,4)
    CRG(6, 1, 7)  // (5,6)
    // u3 on wires 1,3,5,7 -> bits 4,0,1,2
    U3G(0, 4) U3G(1, 0) U3G(2, 1) U3G(3, 2)
    // PAIRS_B: (1,3), (5,7)
    CRG(7, 4, 0)
    CRG(8, 1, 2)
    // e7 now: CR(3,5) and u3(3) commute with q7 observables; u3(7) folded into M7.
    float e7l = quadForm<4>(s, M6[3], M6[4], M6[5]);
    // (3,5)
    CRG(9, 0, 1)
    // e3: u3(3) folded into M3.
    float e3l = quadForm<1>(s, M6[0], M6[1], M6[2]);
#undef CRG
#undef U3G
    u64 e = pk(e3l, e7l);
#pragma unroll
    for (int o = 16; o > 0; o >>= 1) e = f2add(e, shx64(e, o));
    upk(e, e3, e7);   // all lanes hold the totals
}

__global__ __launch_bounds__(256) void qcnn_kernel(
    const float* __restrict__ theta, const float* __restrict__ phi,
    const float* __restrict__ angles_x, const float* __restrict__ angles_y,
    const float* __restrict__ angles_z,
    const float* __restrict__ u3_x, const float* __restrict__ u3_y,
    const float* __restrict__ u3_z,
    const float* __restrict__ W1, const float* __restrict__ b1,
    const float* __restrict__ W2, const float* __restrict__ b2,
    float* __restrict__ out, int B)
{
    __shared__ u64 shCR[3 * 10 * 5];
    __shared__ u64 shU3[3 * 6 * 8];
    __shared__ u64 shBuf[8 * 576];     // per-warp DOUBLE transpose buffer
    __shared__ float shM[18];          // fold consts: m3,w2r3,w2i3,m7,w2r7,w2i7 per branch
    __shared__ float shW1[72], shB1[12], shW2[12];
    __shared__ float shB2;

    int tid = threadIdx.x;
    if (tid < 30) {
        int b = tid / 10, i = tid % 10;
        const float* ang = (b == 0) ? angles_x : (b == 1) ? angles_y : angles_z;
        float sn, c;
        sincosf(0.5f * ang[i], &sn, &c);
        u64* g = &shCR[tid * 5];
        g[0] = pk(c, c);
        g[1] = pk(sn, sn);
        g[2] = pk(-sn, -sn);
        g[3] = pk(sn, -sn);
        g[4] = pk(-sn, sn);
    }
    if (tid >= 32 && tid < 50) {
        int k = tid - 32;
        int b = k / 6, i = k % 6;
        const float* up = ((b == 0) ? u3_x : (b == 1) ? u3_y : u3_z) + i * 3;
        float th = up[0], ph = up[1], lm = up[2];
        float sn, c;    sincosf(0.5f * th, &sn, &c);
        float sl, cl;   sincosf(lm, &sl, &cl);
        float sp, cp;   sincosf(ph, &sp, &cp);
        float spl, cpl; sincosf(ph + lm, &spl, &cpl);
        u64* g = &shU3[k * 8];
        g[0] = pk(c, c);                 g[1] = pk(0.f, 0.f);
        g[2] = pk(-cl * sn, -cl * sn);   g[3] = pk(sl * sn, -sl * sn);
        g[4] = pk(cp * sn, cp * sn);     g[5] = pk(-sp * sn, sp * sn);
        g[6] = pk(cpl * c, cpl * c);     g[7] = pk(-spl * c, spl * c);
    }
    if (tid >= 50 && tid < 56) {
        // measurement fold: M = u3†Zu3
        int k2 = tid - 50;
        int b = k2 / 2, wire = k2 % 2;
        const float* up = ((b == 0) ? u3_x : (b == 1) ? u3_y : u3_z) + (4 + wire) * 3;
        float th = up[0], lm = up[2];
        float st, ct; sincosf(th, &st, &ct);
        float sl, cl; sincosf(lm, &sl, &cl);
        float* m = &shM[b * 6 + wire * 3];
        m[0] = ct;
        m[1] = -2.f * st * cl;
        m[2] =  2.f * st * sl;
    }
    if (tid >= 64 && tid < 136)  shW1[tid - 64] = W1[tid - 64];
    if (tid >= 136 && tid < 148) shB1[tid - 136] = b1[tid - 136];
    if (tid >= 148 && tid < 160) shW2[tid - 148] = W2[tid - 148];
    if (tid == 160) shB2 = b2[0];
    __syncthreads();

    int warp = tid >> 5;
    int lane = tid & 31;
    int batch = blockIdx.x * 8 + warp;
    if (batch >= B) return;

    float th = theta[batch];
    float ph = phi[batch];

    float sy, cy;
    sincosf(0.5f * th, &sy, &cy);
    u64 cc = pk(cy, cy), pp = pk(sy, sy), nn = pk(-sy, -sy);

    // Rz-layer diagonal tables
    float c1x, c1y; sincosf(ph, &c1y, &c1x);
    float cl0x, cl0y; sincosf(ph * (float)(__popc(lane) - 4), &cl0y, &cl0x);
    float px[4], py[4];
    px[0] = cl0x; py[0] = cl0y;
    px[1] = px[0] * c1x - py[0] * c1y; py[1] = px[0] * c1y + py[0] * c1x;
    px[2] = px[1] * c1x - py[1] * c1y; py[2] = px[1] * c1y + py[1] * c1x;
    px[3] = px[2] * c1x - py[2] * c1y; py[3] = px[2] * c1y + py[2] * c1x;
    const int POPC[8] = {0, 1, 1, 2, 1, 2, 2, 3};

    // ---- transpose addressing ----
    u64* buf0 = &shBuf[warp * 576];
    u64* buf1 = buf0 + 288;
    int low3 = lane & 7, hi2 = (lane >> 3) & 3;
    u64* baseA0 = buf0 + low3 + 72 * hi2;
    u64* baseB0 = buf0 + 9 * low3 + 72 * hi2;
    u64* baseB1 = buf1 + 9 * low3 + 72 * hi2;
    int l0 = lane & 1, l1 = (lane >> 1) & 1, l2 = (lane >> 2) & 1;
    int l3 = (lane >> 3) & 1, l4 = (lane >> 4) & 1;
    int adrR[8];
#pragma unroll
    for (int j = 0; j < 8; j++) {
        int j0 = j & 1, j1 = (j >> 1) & 1, j2 = (j >> 2) & 1;
        int x0 = l0 ^ j2, x1 = l1 ^ l0 ^ j2, x2 = l2 ^ l1;
        int x3 = j0 ^ l2, x4 = l3 ^ j0, x5 = j1 ^ l3, x6 = l4 ^ j1, x7 = l4 ^ j2;
        adrR[j] = (x0 + 2 * x1 + 4 * x2) + 9 * (x3 + 2 * x5 + 4 * x7) + 72 * (x4 + 2 * x6);
    }

    // ---- cycle 1: closed-form product state with ring folded ----
    u64 s[8];
    {
        float tn = sy / cy;
        float zr = tn * c1x, zi = tn * c1y;
        float cy2 = cy * cy, cy4 = cy2 * cy2, cy8 = cy4 * cy4;
        float c2r = c1x * c1x - c1y * c1y, c2i = 2.f * c1x * c1y;
        float c4r = c2r * c2r - c2i * c2i, c4i = 2.f * c2r * c2i;
        float tr = cy8 * c4r, ti = -cy8 * c4i;
        u64 myT = 0;
#pragma unroll
        for (int p = 0; p < 9; p++) {
            if (lane == p) myT = pk(tr, ti);
            float nr = tr * zr - ti * zi;
            ti = tr * zi + ti * zr;
            tr = nr;
        }
        if (lane < 9) buf0[lane] = myT;
        __syncwarp();
        int lb = l0 | ((l1 ^ l0) << 1) | ((l2 ^ l1) << 2) | (l2 << 3) | (l3 * 48) | (l4 * 192);
        const int JB[8] = {0, 24, 96, 120, 131, 155, 227, 251};
#pragma unroll
        for (int j = 0; j < 8; j++) s[j] = buf0[__popc(lb ^ JB[j])];
        __syncwarp();
    }

    // ---- cycles 2..4 ----
#pragma unroll 1
    for (int cyc = 0; cyc < 3; cyc++) {
        applyRy<0>(s, cc, pp, nn, lane);
        applyRy<1>(s, cc, pp, nn, lane);
        applyRy<2>(s, cc, pp, nn, lane);
#pragma unroll
        for (int j = 0; j < 8; j++) baseA0[9 * j] = s[j];
        __syncwarp();
#pragma unroll
        for (int j = 0; j < 8; j++) s[j] = baseB0[j];
        applyRy<0>(s, cc, pp, nn, lane);
        applyRy<1>(s, cc, pp, nn, lane);
        applyRy<2>(s, cc, pp, nn, lane);
        applyRy<6>(s, cc, pp, nn, lane);
        applyRy<7>(s, cc, pp, nn, lane);
#pragma unroll
        for (int j = 0; j < 8; j++) {
            float x, y; upk(s[j], x, y);
            int d = POPC[j];
            s[j] = pk(px[d] * x - py[d] * y, px[d] * y + py[d] * x);
        }
#pragma unroll
        for (int j = 0; j < 8; j++) baseB1[j] = s[j];
        __syncwarp();
#pragma unroll
        for (int j = 0; j < 8; j++) s[j] = buf1[adrR[j]];
    }

    // ---- save psi0 ----
    u64 p0[8];
#pragma unroll
    for (int j = 0; j < 8; j++) p0[j] = s[j];

    float feats[6];

    runBranch<0>(s, &shCR[0],   &shU3[0],  &shM[0],  lane, feats[0], feats[1]);
#pragma unroll
    for (int j = 0; j < 8; j++) s[j] = p0[j];
    runBranch<1>(s, &shCR[50],  &shU3[48], &shM[6],  lane, feats[2], feats[3]);
#pragma unroll
    for (int j = 0; j < 8; j++) s[j] = p0[j];
    runBranch<2>(s, &shCR[100], &shU3[96], &shM[12], lane, feats[4], feats[5]);

    // ---- MLP: parallel across lanes 0..11 (all lanes hold feats) ----
    {
        float o = 0.f;
        if (lane < 12) {
            float a = shB1[lane];
#pragma unroll
            for (int f = 0; f < 6; f++) a = fmaf(shW1[lane * 6 + f], feats[f], a);
            o = tanhf(a) * shW2[lane];
        }
#pragma unroll
        for (int w = 16; w > 0; w >>= 1) o += __shfl_xor_sync(FULLMASK, o, w);
        if (lane == 0) out[batch] = 1.f / (1.f + expf(-(o + shB2)));
    }
}

extern "C" void kernel_launch(void* const* d_in, const int* in_sizes, int n_in,
                              void* d_out, int out_size) {
    const float* theta    = (const float*)d_in[0];
    const float* phi      = (const float*)d_in[1];
    const float* angles_x = (const float*)d_in[2];
    const float* angles_y = (const float*)d_in[3];
    const float* angles_z = (const float*)d_in[4];
    const float* u3_x     = (const float*)d_in[5];
    const float* u3_y     = (const float*)d_in[6];
    const float* u3_z     = (const float*)d_in[7];
    const float* W1       = (const float*)d_in[8];
    const float* b1       = (const float*)d_in[9];
    const float* W2       = (const float*)d_in[10];
    const float* b2       = (const float*)d_in[11];
    float* out = (float*)d_out;

    int B = in_sizes[0];
    int blocks = (B + 7) / 8;
    qcnn_kernel<<<blocks, 256>>>(theta, phi, angles_x, angles_y, angles_z,
                                 u3_x, u3_y, u3_z, W1, b1, W2, b2, out, B);
}

// round 14
// speedup vs baseline: 1.3674x; 1.0024x over previous
#include <cuda_runtime.h>
#include <cuda_bf16.h>

#define FULLMASK 0xffffffffu
typedef unsigned long long u64;

// Qubit -> amplitude-index-bit mapping (layout A):
//   q3->bit0, q5->bit1, q7->bit2  (register bits: j index 0..7)
//   q0->L0, q1->L1, q2->L2, q4->L3, q6->L4  (lane bits)
// amp index = (lane << 3) | j ; amplitude = packed (re, im) in one u64.

__device__ __forceinline__ u64 pk(float lo, float hi) {
    u64 r; asm("mov.b64 %0, {%1, %2};" : "=l"(r) : "f"(lo), "f"(hi)); return r;
}
__device__ __forceinline__ void upk(u64 v, float& x, float& y) {
    asm("mov.b64 {%0, %1}, %2;" : "=f"(x), "=f"(y) : "l"(v));
}
__device__ __forceinline__ u64 f2mul(u64 a, u64 b) {
    u64 r; asm("mul.rn.f32x2 %0, %1, %2;" : "=l"(r) : "l"(a), "l"(b)); return r;
}
__device__ __forceinline__ u64 f2fma(u64 a, u64 b, u64 c) {
    u64 r; asm("fma.rn.f32x2 %0, %1, %2, %3;" : "=l"(r) : "l"(a), "l"(b), "l"(c)); return r;
}
__device__ __forceinline__ u64 f2add(u64 a, u64 b) {
    u64 r; asm("add.rn.f32x2 %0, %1, %2;" : "=l"(r) : "l"(a), "l"(b)); return r;
}
__device__ __forceinline__ u64 swp(u64 v) { float x, y; upk(v, x, y); return pk(y, x); }
__device__ __forceinline__ u64 shx64(u64 v, int m) { return __shfl_xor_sync(FULLMASK, v, m); }
__device__ __forceinline__ u64 shxswp(u64 v, int m) {
    float x, y; upk(v, x, y);
    float sx = __shfl_xor_sync(FULLMASK, x, m);
    float sy = __shfl_xor_sync(FULLMASK, y, m);
    return pk(sy, sx);
}

// ---- Ry on index-bit Tb ----
template <int Tb>
__device__ __forceinline__ void applyRy(u64 s[8], u64 cc, u64 pp, u64 nn, int lane) {
    if constexpr (Tb < 3) {
        constexpr int m = 1 << Tb;
#pragma unroll
        for (int j = 0; j < 8; j++) {
            if (!(j & m)) {
                u64 a = s[j], b = s[j | m];
                s[j]     = f2fma(cc, a, f2mul(nn, b));
                s[j | m] = f2fma(cc, b, f2mul(pp, a));
            }
        }
    } else {
        constexpr int lb = 1 << (Tb - 3);
        u64 sg = (lane & lb) ? pp : nn;
#pragma unroll
        for (int j = 0; j < 8; j++) {
            u64 o = shx64(s[j], lb);
            s[j] = f2fma(cc, s[j], f2mul(sg, o));
        }
    }
}

// ---- controlled rotation: K=0 rx, K=1 ry ----
// G[0]=(c,c) G[1]=(s,s) G[2]=(-s,-s) G[3]=(s,-s) G[4]=(-s,s)
template <int K, int Cb, int Tb>
__device__ __forceinline__ void applyCR(u64 s[8], const u64* __restrict__ G, int lane) {
    u64 cc = G[0];
    if constexpr (Tb < 3) {
        constexpr int tm = 1 << Tb;
        bool lc = (Cb >= 3) ? (((lane >> (Cb - 3)) & 1) != 0) : false;
#pragma unroll
        for (int j = 0; j < 8; j++) {
            if (!(j & tm) && (Cb >= 3 || ((j >> Cb) & 1))) {
                u64 a = s[j], b = s[j | tm], na, nb;
                if constexpr (K == 0) {   // rx
                    u64 pm = G[3];
                    na = f2fma(cc, a, f2mul(pm, swp(b)));
                    nb = f2fma(cc, b, f2mul(pm, swp(a)));
                } else {                  // ry
                    na = f2fma(cc, a, f2mul(G[2], b));
                    nb = f2fma(cc, b, f2mul(G[1], a));
                }
                if constexpr (Cb < 3) { s[j] = na; s[j | tm] = nb; }
                else { if (lc) { s[j] = na; s[j | tm] = nb; } }
            }
        }
    } else {
        constexpr int lb = 1 << (Tb - 3);
        u64 sg = (lane & lb) ? G[1] : G[2];
        if constexpr (Cb < 3) {
#pragma unroll
            for (int j = 0; j < 8; j++) {
                if (j & (1 << Cb)) {
                    if constexpr (K == 0) {
                        u64 os = shxswp(s[j], lb);
                        s[j] = f2fma(cc, s[j], f2mul(G[3], os));
                    } else {
                        u64 o = shx64(s[j], lb);
                        s[j] = f2fma(cc, s[j], f2mul(sg, o));
                    }
                }
            }
        } else {
            bool lc = ((lane >> (Cb - 3)) & 1) != 0;
#pragma unroll
            for (int j = 0; j < 8; j++) {
                u64 r;
                if constexpr (K == 0) r = f2fma(cc, s[j], f2mul(G[3], shxswp(s[j], lb)));
                else                  r = f2fma(cc, s[j], f2mul(sg, shx64(s[j], lb)));
                if (lc) s[j] = r;
            }
        }
    }
}

// ---- general u3 gate: uXr=(re,re), uXi=(-im,im) ----
template <int Tb>
__device__ __forceinline__ void applyU3(u64 s[8], const u64* __restrict__ U, int lane) {
    if constexpr (Tb < 3) {
        constexpr int m = 1 << Tb;
#pragma unroll
        for (int j = 0; j < 8; j++) {
            if (!(j & m)) {
                u64 a = s[j], b = s[j | m];
                u64 as = swp(a), bs = swp(b);
                s[j]     = f2fma(U[0], a, f2fma(U[2], b, f2mul(U[3], bs)));
                s[j | m] = f2fma(U[4], a, f2fma(U[5], as, f2fma(U[6], b, f2mul(U[7], bs))));
            }
        }
    } else {
        constexpr int lb = 1 << (Tb - 3);
        bool hi = (lane & lb) != 0;
        u64 Ar = hi ? U[6] : U[0];
        u64 Ai = hi ? U[7] : U[1];
        u64 Br = hi ? U[4] : U[2];
        u64 Bi = hi ? U[5] : U[3];
#pragma unroll
        for (int j = 0; j < 8; j++) {
            float x, y; upk(s[j], x, y);
            float ox = __shfl_xor_sync(FULLMASK, x, lb);
            float oy = __shfl_xor_sync(FULLMASK, y, lb);
            u64 o = pk(ox, oy), os = pk(oy, ox), ss2 = pk(y, x);
            s[j] = f2fma(Ar, s[j], f2fma(Ai, ss2, f2fma(Br, o, f2mul(Bi, os))));
        }
    }
}

// quadratic-form partial over pairs (a, a|bit):
//   m*(qa - qb) + w2r*Re(psi_a* psi_b) + w2i*Im(psi_a* psi_b)
template <int bit>
__device__ __forceinline__ float quadForm(const u64 s[8], float m, float w2r, float w2i) {
    float acc = 0.f;
#pragma unroll
    for (int j = 0; j < 8; j++) {
        if (!(j & bit)) {
            u64 A = s[j], B = s[j | bit];
            u64 qa = f2mul(A, A), qb = f2mul(B, B);
            u64 rr = f2mul(A, B), ii = f2mul(A, swp(B));
            float qax, qay, qbx, qby, rx, ry, ix, iy;
            upk(qa, qax, qay); upk(qb, qbx, qby);
            upk(rr, rx, ry);   upk(ii, ix, iy);
            acc = fmaf(m, (qax + qay) - (qbx + qby), acc);
            acc = fmaf(w2r, rx + ry, acc);
            acc = fmaf(w2i, ix - iy, acc);
        }
    }
    return acc;
}

// ---- x / y branch: returns unreduced packed (e3, e7) ----
template <int K>
__device__ __forceinline__ u64 runBranch(u64 s[8], const u64* __restrict__ CR,
                                         const u64* __restrict__ UM,
                                         const float* __restrict__ M6, int lane) {
#define CRG(i, Cb, Tb) applyCR<K, Cb, Tb>(s, CR + (i) * 5, lane);
#define U3G(i, Tb) applyU3<Tb>(s, UM + (i) * 8, lane);
    // PAIRS_A
    CRG(0, 3, 4)  // (0,1)
    CRG(1, 5, 0)  // (2,3)
    CRG(2, 6, 1)  // (4,5)
    CRG(3, 7, 2)  // (6,7)
    CRG(4, 4, 5)  // (1,2)
    CRG(5, 0, 6)  // (3,4)
    CRG(6, 1, 7)  // (5,6)
    // u3 on wires 1,3,5,7 -> bits 4,0,1,2
    U3G(0, 4) U3G(1, 0) U3G(2, 1) U3G(3, 2)
    // PAIRS_B: (1,3), (5,7)
    CRG(7, 4, 0)
    CRG(8, 1, 2)
    // e7 now: CR(3,5) / u3(3) commute with q7 observables; u3(7) folded into M7.
    float e7l = quadForm<4>(s, M6[3], M6[4], M6[5]);
    // (3,5)
    CRG(9, 0, 1)
    // e3: u3(3) folded into M3.
    float e3l = quadForm<1>(s, M6[0], M6[1], M6[2]);
#undef CRG
#undef U3G
    return pk(e3l, e7l);
}

// ---- z branch: PAIRS_A as precomputed diagonal table; PAIRS_B folded into
//      measurement coefficients. Returns unreduced packed (e3, e7). ----
__device__ __forceinline__ u64 runBranchZ(u64 s[8],
                                          const u64* __restrict__ ZAa,
                                          const u64* __restrict__ ZAb,
                                          const u64* __restrict__ UM,
                                          const float* __restrict__ Z3,
                                          const float* __restrict__ Z7,
                                          const float* __restrict__ Zm,
                                          int lane) {
    // combined PAIRS_A diagonal
#pragma unroll
    for (int j = 0; j < 8; j++) {
        u64 aa = ZAa[j * 32 + lane], bn = ZAb[j * 32 + lane];
        s[j] = f2fma(aa, s[j], f2mul(bn, swp(s[j])));
    }
    // u3 on wires 1,3,5,7 -> bits 4,0,1,2
    applyU3<4>(s, UM + 0 * 8, lane);
    applyU3<0>(s, UM + 1 * 8, lane);
    applyU3<1>(s, UM + 2 * 8, lane);
    applyU3<2>(s, UM + 3 * 8, lane);
    // measurements with PAIRS_B diagonal folded into coefficients
    int q1 = (lane >> 1) & 1;
    float m3 = Zm[0], m7 = Zm[1];
    float w3r0 = Z3[(2 * q1 + 0) * 2 + 0], w3i0 = Z3[(2 * q1 + 0) * 2 + 1];
    float w3r1 = Z3[(2 * q1 + 1) * 2 + 0], w3i1 = Z3[(2 * q1 + 1) * 2 + 1];
    float w7r0 = Z7[0], w7i0 = Z7[1], w7r1 = Z7[2], w7i1 = Z7[3];
    float e3l = 0.f, e7l = 0.f;
    // e3: pairs (j, j|1), j in {0,2,4,6}; q5 = (j>>1)&1
#pragma unroll
    for (int jj = 0; jj < 4; jj++) {
        int j = jj * 2;
        float wr = (jj & 1) ? w3r1 : w3r0;
        float wi = (jj & 1) ? w3i1 : w3i0;
        u64 A = s[j], B = s[j | 1];
        u64 qa = f2mul(A, A), qb = f2mul(B, B);
        u64 rr = f2mul(A, B), ii = f2mul(A, swp(B));
        float qax, qay, qbx, qby, rx, ry, ix, iy;
        upk(qa, qax, qay); upk(qb, qbx, qby);
        upk(rr, rx, ry);   upk(ii, ix, iy);
        e3l = fmaf(m3, (qax + qay) - (qbx + qby), e3l);
        e3l = fmaf(wr, rx + ry, e3l);
        e3l = fmaf(wi, ix - iy, e3l);
    }
    // e7: pairs (j, j|4), j in {0..3}; q5 = (j>>1)&1
#pragma unroll
    for (int j = 0; j < 4; j++) {
        float wr = ((j >> 1) & 1) ? w7r1 : w7r0;
        float wi = ((j >> 1) & 1) ? w7i1 : w7i0;
        u64 A = s[j], B = s[j | 4];
        u64 qa = f2mul(A, A), qb = f2mul(B, B);
        u64 rr = f2mul(A, B), ii = f2mul(A, swp(B));
        float qax, qay, qbx, qby, rx, ry, ix, iy;
        upk(qa, qax, qay); upk(qb, qbx, qby);
        upk(rr, rx, ry);   upk(ii, ix, iy);
        e7l = fmaf(m7, (qax + qay) - (qbx + qby), e7l);
        e7l = fmaf(wr, rx + ry, e7l);
        e7l = fmaf(wi, ix - iy, e7l);
    }
    return pk(e3l, e7l);
}

__global__ __launch_bounds__(256) void qcnn_kernel(
    const float* __restrict__ theta, const float* __restrict__ phi,
    const float* __restrict__ angles_x, const float* __restrict__ angles_y,
    const float* __restrict__ angles_z,
    const float* __restrict__ u3_x, const float* __restrict__ u3_y,
    const float* __restrict__ u3_z,
    const float* __restrict__ W1, const float* __restrict__ b1,
    const float* __restrict__ W2, const float* __restrict__ b2,
    float* __restrict__ out, int B)
{
    __shared__ u64 shCR[2 * 10 * 5];   // x,y rotation consts
    __shared__ u64 shU3[3 * 6 * 8];
    __shared__ u64 shBuf[8 * 576];     // per-warp DOUBLE transpose buffer
    __shared__ u64 shZAa[256], shZAb[256];  // z PAIRS_A diagonal table
    __shared__ float shM[12];          // x,y fold consts
    __shared__ float shZ3[8], shZ7[4], shZm[2];  // z folded measurement consts
    __shared__ float shW1[72], shB1[12], shW2[12];
    __shared__ float shB2;

    int tid = threadIdx.x;
    // z PAIRS_A diagonal table: every thread computes one entry
    {
        int j = tid >> 5, ln = tid & 31;
        float q[8];
        q[0] = (float)(ln & 1);        q[1] = (float)((ln >> 1) & 1);
        q[2] = (float)((ln >> 2) & 1); q[4] = (float)((ln >> 3) & 1);
        q[6] = (float)((ln >> 4) & 1);
        q[3] = (float)(j & 1); q[5] = (float)((j >> 1) & 1); q[7] = (float)((j >> 2) & 1);
        const int pc[7] = {0, 2, 4, 6, 1, 3, 5};
        const int pt[7] = {1, 3, 5, 7, 2, 4, 6};
        float ang = 0.f;
#pragma unroll
        for (int i = 0; i < 7; i++)
            ang += q[pc[i]] * (q[pt[i]] > 0.5f ? 0.5f : -0.5f) * angles_z[i];
        float sn, cs; sincosf(ang, &sn, &cs);
        shZAa[tid] = pk(cs, cs);
        shZAb[tid] = pk(-sn, sn);
    }
    if (tid < 20) {
        int b = tid / 10, i = tid % 10;
        const float* ang = (b == 0) ? angles_x : angles_y;
        float sn, c;
        sincosf(0.5f * ang[i], &sn, &c);
        u64* g = &shCR[tid * 5];
        g[0] = pk(c, c);
        g[1] = pk(sn, sn);
        g[2] = pk(-sn, -sn);
        g[3] = pk(sn, -sn);
        g[4] = pk(-sn, sn);
    }
    if (tid >= 32 && tid < 50) {
        int k = tid - 32;
        int b = k / 6, i = k % 6;
        const float* up = ((b == 0) ? u3_x : (b == 1) ? u3_y : u3_z) + i * 3;
        float th = up[0], ph = up[1], lm = up[2];
        float sn, c;    sincosf(0.5f * th, &sn, &c);
        float sl, cl;   sincosf(lm, &sl, &cl);
        float sp, cp;   sincosf(ph, &sp, &cp);
        float spl, cpl; sincosf(ph + lm, &spl, &cpl);
        u64* g = &shU3[k * 8];
        g[0] = pk(c, c);                 g[1] = pk(0.f, 0.f);
        g[2] = pk(-cl * sn, -cl * sn);   g[3] = pk(sl * sn, -sl * sn);
        g[4] = pk(cp * sn, cp * sn);     g[5] = pk(-sp * sn, sp * sn);
        g[6] = pk(cpl * c, cpl * c);     g[7] = pk(-spl * c, spl * c);
    }
    if (tid >= 50 && tid < 54) {
        // x,y measurement folds: M = u3†Zu3
        int k2 = tid - 50;
        int b = k2 / 2, wire = k2 % 2;
        const float* up = ((b == 0) ? u3_x : u3_y) + (4 + wire) * 3;
        float th = up[0], lm = up[2];
        float st, ct; sincosf(th, &st, &ct);
        float sl, cl; sincosf(lm, &sl, &cl);
        float* m = &shM[b * 6 + wire * 3];
        m[0] = ct;
        m[1] = -2.f * st * cl;
        m[2] =  2.f * st * sl;
    }
    if (tid >= 56 && tid < 60) {
        // z e3 coefficient variants: delta = q1*az[7] + (q5? +az[9]/2 : -az[9]/2)
        int v = tid - 56;
        float q1v = (float)((v >> 1) & 1), q5v = (float)(v & 1);
        float del = q1v * angles_z[7] + (q5v > 0.5f ? 0.5f : -0.5f) * angles_z[9];
        float sd, cd; sincosf(del, &sd, &cd);
        float th = u3_z[12], lm = u3_z[14];
        float st, ct; sincosf(th, &st, &ct);
        float sl, cl; sincosf(lm, &sl, &cl);
        float w2r = -2.f * st * cl, w2i = 2.f * st * sl;
        shZ3[v * 2 + 0] = w2r * cd + w2i * sd;
        shZ3[v * 2 + 1] = -w2r * sd + w2i * cd;
        if (v == 0) shZm[0] = ct;
    }
    if (tid >= 60 && tid < 62) {
        // z e7 coefficient variants: delta = q5*az[8]
        int v = tid - 60;
        float del = (float)v * angles_z[8];
        float sd, cd; sincosf(del, &sd, &cd);
        float th = u3_z[15], lm = u3_z[17];
        float st, ct; sincosf(th, &st, &ct);
        float sl, cl; sincosf(lm, &sl, &cl);
        float w2r = -2.f * st * cl, w2i = 2.f * st * sl;
        shZ7[v * 2 + 0] = w2r * cd + w2i * sd;
        shZ7[v * 2 + 1] = -w2r * sd + w2i * cd;
        if (v == 0) shZm[1] = ct;
    }
    if (tid >= 64 && tid < 136)  shW1[tid - 64] = W1[tid - 64];
    if (tid >= 136 && tid < 148) shB1[tid - 136] = b1[tid - 136];
    if (tid >= 148 && tid < 160) shW2[tid - 148] = W2[tid - 148];
    if (tid == 160) shB2 = b2[0];
    __syncthreads();

    int warp = tid >> 5;
    int lane = tid & 31;
    int batch = blockIdx.x * 8 + warp;
    if (batch >= B) return;

    float th = theta[batch];
    float ph = phi[batch];

    float sy, cy;
    sincosf(0.5f * th, &sy, &cy);
    u64 cc = pk(cy, cy), pp = pk(sy, sy), nn = pk(-sy, -sy);

    // Rz-layer diagonal tables
    float c1x, c1y; sincosf(ph, &c1y, &c1x);
    float cl0x, cl0y; sincosf(ph * (float)(__popc(lane) - 4), &cl0y, &cl0x);
    float px[4], py[4];
    px[0] = cl0x; py[0] = cl0y;
    px[1] = px[0] * c1x - py[0] * c1y; py[1] = px[0] * c1y + py[0] * c1x;
    px[2] = px[1] * c1x - py[1] * c1y; py[2] = px[1] * c1y + py[1] * c1x;
    px[3] = px[2] * c1x - py[2] * c1y; py[3] = px[2] * c1y + py[2] * c1x;
    const int POPC[8] = {0, 1, 1, 2, 1, 2, 2, 3};

    // ---- transpose addressing ----
    u64* buf0 = &shBuf[warp * 576];
    u64* buf1 = buf0 + 288;
    int low3 = lane & 7, hi2 = (lane >> 3) & 3;
    u64* baseA0 = buf0 + low3 + 72 * hi2;
    u64* baseB0 = buf0 + 9 * low3 + 72 * hi2;
    u64* baseB1 = buf1 + 9 * low3 + 72 * hi2;
    int l0 = lane & 1, l1 = (lane >> 1) & 1, l2 = (lane >> 2) & 1;
    int l3 = (lane >> 3) & 1, l4 = (lane >> 4) & 1;
    int adrR[8];
#pragma unroll
    for (int j = 0; j < 8; j++) {
        int j0 = j & 1, j1 = (j >> 1) & 1, j2 = (j >> 2) & 1;
        int x0 = l0 ^ j2, x1 = l1 ^ l0 ^ j2, x2 = l2 ^ l1;
        int x3 = j0 ^ l2, x4 = l3 ^ j0, x5 = j1 ^ l3, x6 = l4 ^ j1, x7 = l4 ^ j2;
        adrR[j] = (x0 + 2 * x1 + 4 * x2) + 9 * (x3 + 2 * x5 + 4 * x7) + 72 * (x4 + 2 * x6);
    }

    // ---- cycle 1: closed-form product state with ring folded ----
    u64 s[8];
    {
        float tn = sy / cy;
        float zr = tn * c1x, zi = tn * c1y;
        float cy2 = cy * cy, cy4 = cy2 * cy2, cy8 = cy4 * cy4;
        float c2r = c1x * c1x - c1y * c1y, c2i = 2.f * c1x * c1y;
        float c4r = c2r * c2r - c2i * c2i, c4i = 2.f * c2r * c2i;
        float tr = cy8 * c4r, ti = -cy8 * c4i;
        u64 myT = 0;
#pragma unroll
        for (int p = 0; p < 9; p++) {
            if (lane == p) myT = pk(tr, ti);
            float nr = tr * zr - ti * zi;
            ti = tr * zi + ti * zr;
            tr = nr;
        }
        if (lane < 9) buf0[lane] = myT;
        __syncwarp();
        int lb = l0 | ((l1 ^ l0) << 1) | ((l2 ^ l1) << 2) | (l2 << 3) | (l3 * 48) | (l4 * 192);
        const int JB[8] = {0, 24, 96, 120, 131, 155, 227, 251};
#pragma unroll
        for (int j = 0; j < 8; j++) s[j] = buf0[__popc(lb ^ JB[j])];
        __syncwarp();
    }

    // ---- cycles 2..4 ----
#pragma unroll 1
    for (int cyc = 0; cyc < 3; cyc++) {
        applyRy<0>(s, cc, pp, nn, lane);
        applyRy<1>(s, cc, pp, nn, lane);
        applyRy<2>(s, cc, pp, nn, lane);
#pragma unroll
        for (int j = 0; j < 8; j++) baseA0[9 * j] = s[j];
        __syncwarp();
#pragma unroll
        for (int j = 0; j < 8; j++) s[j] = baseB0[j];
        applyRy<0>(s, cc, pp, nn, lane);
        applyRy<1>(s, cc, pp, nn, lane);
        applyRy<2>(s, cc, pp, nn, lane);
        applyRy<6>(s, cc, pp, nn, lane);
        applyRy<7>(s, cc, pp, nn, lane);
#pragma unroll
        for (int j = 0; j < 8; j++) {
            float x, y; upk(s[j], x, y);
            int d = POPC[j];
            s[j] = pk(px[d] * x - py[d] * y, px[d] * y + py[d] * x);
        }
#pragma unroll
        for (int j = 0; j < 8; j++) baseB1[j] = s[j];
        __syncwarp();
#pragma unroll
        for (int j = 0; j < 8; j++) s[j] = buf1[adrR[j]];
    }

    // ---- save psi0 ----
    u64 p0[8];
#pragma unroll
    for (int j = 0; j < 8; j++) p0[j] = s[j];

    u64 ex = runBranch<0>(s, &shCR[0],  &shU3[0],  &shM[0], lane);
#pragma unroll
    for (int j = 0; j < 8; j++) s[j] = p0[j];
    u64 ey = runBranch<1>(s, &shCR[50], &shU3[48], &shM[6], lane);
#pragma unroll
    for (int j = 0; j < 8; j++) s[j] = p0[j];
    u64 ez = runBranchZ(s, shZAa, shZAb, &shU3[96], shZ3, shZ7, shZm, lane);

    // batched reductions (3 independent chains)
#pragma unroll
    for (int o = 16; o > 0; o >>= 1) {
        ex = f2add(ex, shx64(ex, o));
        ey = f2add(ey, shx64(ey, o));
        ez = f2add(ez, shx64(ez, o));
    }
    float feats[6];
    upk(ex, feats[0], feats[1]);
    upk(ey, feats[2], feats[3]);
    upk(ez, feats[4], feats[5]);

    // ---- MLP: parallel across lanes 0..11 ----
    {
        float o = 0.f;
        if (lane < 12) {
            float a = shB1[lane];
#pragma unroll
            for (int f = 0; f < 6; f++) a = fmaf(shW1[lane * 6 + f], feats[f], a);
            o = tanhf(a) * shW2[lane];
        }
#pragma unroll
        for (int w = 16; w > 0; w >>= 1) o += __shfl_xor_sync(FULLMASK, o, w);
        if (lane == 0) out[batch] = 1.f / (1.f + expf(-(o + shB2)));
    }
}

extern "C" void kernel_launch(void* const* d_in, const int* in_sizes, int n_in,
                              void* d_out, int out_size) {
    const float* theta    = (const float*)d_in[0];
    const float* phi      = (const float*)d_in[1];
    const float* angles_x = (const float*)d_in[2];
    const float* angles_y = (const float*)d_in[3];
    const float* angles_z = (const float*)d_in[4];
    const float* u3_x     = (const float*)d_in[5];
    const float* u3_y     = (const float*)d_in[6];
    const float* u3_z     = (const float*)d_in[7];
    const float* W1       = (const float*)d_in[8];
    const float* b1       = (const float*)d_in[9];
    const float* W2       = (const float*)d_in[10];
    const float* b2       = (const float*)d_in[11];
    float* out = (float*)d_out;

    int B = in_sizes[0];
    int blocks = (B + 7) / 8;
    qcnn_kernel<<<blocks, 256>>>(theta, phi, angles_x, angles_y, angles_z,
                                 u3_x, u3_y, u3_z, W1, b1, W2, b2, out, B);
}